// round 2
// baseline (speedup 1.0000x reference)
#include <cuda_runtime.h>
#include <cuda_bf16.h>
#include <math.h>

// Problem constants
#define Bb 4
#define Tt 1024
#define Cc 1024
#define Hh 16
#define Ll 256
#define Dd 64
#define NROW (Bb*Tt)   // 4096

// Scratch (allocation-free: __device__ globals)
__device__ float g_kv_down[NROW * Ll];
__device__ float g_q_down [NROW * Ll];
__device__ float g_k  [NROW * Cc];
__device__ float g_q  [NROW * Cc];
__device__ float g_v  [NROW * Cc];
__device__ float g_ctx[NROW * Cc];

// ---------------------------------------------------------------------------
// Generic tiled SGEMM: C[M,N] = A[M,K] @ B[K,N] (+bias[N])
// BM=BN=64, BK=16, 256 threads, 4x4 microtile per thread.
// ---------------------------------------------------------------------------
__global__ __launch_bounds__(256) void sgemm64(
    const float* __restrict__ A, const float* __restrict__ B,
    float* __restrict__ C, int M, int N, int K,
    const float* __restrict__ bias)
{
    __shared__ float As[16][64];   // transposed: As[k][m]
    __shared__ float Bs[16][64];

    const int tid = threadIdx.x;
    const int tx = tid & 15;       // 0..15 -> 4 N-cols each
    const int ty = tid >> 4;       // 0..15 -> 4 M-rows each
    const int bm = blockIdx.y * 64;
    const int bn = blockIdx.x * 64;

    float acc[4][4] = {};

    for (int k0 = 0; k0 < K; k0 += 16) {
        // load A tile 64x16 (one float4 per thread)
        {
            int row = tid >> 2;          // 0..63
            int c4  = (tid & 3) * 4;     // 0,4,8,12
            float4 a = *(const float4*)&A[(size_t)(bm + row) * K + k0 + c4];
            As[c4 + 0][row] = a.x;
            As[c4 + 1][row] = a.y;
            As[c4 + 2][row] = a.z;
            As[c4 + 3][row] = a.w;
        }
        // load B tile 16x64 (one float4 per thread)
        {
            int row = tid >> 4;          // 0..15
            int c4  = (tid & 15) * 4;
            *(float4*)&Bs[row][c4] = *(const float4*)&B[(size_t)(k0 + row) * N + bn + c4];
        }
        __syncthreads();

        #pragma unroll
        for (int kk = 0; kk < 16; kk++) {
            float4 a = *(const float4*)&As[kk][ty * 4];
            float4 b = *(const float4*)&Bs[kk][tx * 4];
            float ar[4] = {a.x, a.y, a.z, a.w};
            float br[4] = {b.x, b.y, b.z, b.w};
            #pragma unroll
            for (int i = 0; i < 4; i++)
                #pragma unroll
                for (int j = 0; j < 4; j++)
                    acc[i][j] += ar[i] * br[j];
        }
        __syncthreads();
    }

    float4 bv = {0.f, 0.f, 0.f, 0.f};
    if (bias) bv = *(const float4*)&bias[bn + tx * 4];
    #pragma unroll
    for (int i = 0; i < 4; i++) {
        float4 r;
        r.x = acc[i][0] + bv.x;
        r.y = acc[i][1] + bv.y;
        r.z = acc[i][2] + bv.z;
        r.w = acc[i][3] + bv.w;
        *(float4*)&C[(size_t)(bm + ty * 4 + i) * N + bn + tx * 4] = r;
    }
}

// ---------------------------------------------------------------------------
// Fused flash attention with causal mask, padding mask, interaction bias.
//   scores[b,h,q,k] = causal(k<=q) ? (pad[b,q] ? q.k*scale : -1e9) + inter[b,k,q,h]
//                                  : -inf
//   softmax over k, ctx = attn @ v  -> ctx[b*T+q, h*D+d]
// Q/K/V layouts: [b*T + t, h*D + d] row-major (stride C=1024).
// One block per (q-tile of 64, h, b). 256 threads, 4x4 microtiles.
// ---------------------------------------------------------------------------
__device__ __forceinline__ float redmax16(float v) {
    #pragma unroll
    for (int m = 8; m >= 1; m >>= 1)
        v = fmaxf(v, __shfl_xor_sync(0xffffffffu, v, m));
    return v;
}
__device__ __forceinline__ float redsum16(float v) {
    #pragma unroll
    for (int m = 8; m >= 1; m >>= 1)
        v += __shfl_xor_sync(0xffffffffu, v, m);
    return v;
}

__global__ __launch_bounds__(256) void attn_kernel(
    const float* __restrict__ Qm, const float* __restrict__ Km,
    const float* __restrict__ Vm, const float* __restrict__ inter,
    const int* __restrict__ pad, float* __restrict__ ctx)
{
    extern __shared__ float sm[];
    float* Qs = sm;                  // [64][64]
    float* KP = sm + 64 * 64;        // [64][68]  K tile, reused as P[q][k]
    float* Vs = KP + 64 * 68;        // [64][68]

    const int qt = blockIdx.x;       // 0..15
    const int h  = blockIdx.y;       // 0..15
    const int b  = blockIdx.z;       // 0..3
    const int tid = threadIdx.x;
    const int tx = tid & 15;
    const int ty = tid >> 4;
    const float scale = 0.125f;      // D^-0.5, D=64

    // load Q tile (64 rows x 64 cols)
    for (int i = tid; i < 64 * 16; i += 256) {
        int row = i >> 4, c4 = (i & 15) * 4;
        *(float4*)&Qs[row * 64 + c4] =
            *(const float4*)&Qm[(size_t)(b * Tt + qt * 64 + row) * Cc + h * Dd + c4];
    }

    float m_i[4], l_i[4], o[4][4];
    int qg[4], pm[4];
    #pragma unroll
    for (int i = 0; i < 4; i++) {
        m_i[i] = -INFINITY; l_i[i] = 0.f;
        qg[i] = qt * 64 + ty * 4 + i;
        pm[i] = pad[b * Tt + qg[i]];
        #pragma unroll
        for (int j = 0; j < 4; j++) o[i][j] = 0.f;
    }

    for (int kt = 0; kt <= qt; kt++) {
        __syncthreads();   // previous iteration done with KP/Vs (and Q load on iter 0)
        // load K and V tiles
        for (int i = tid; i < 64 * 16; i += 256) {
            int row = i >> 4, c4 = (i & 15) * 4;
            size_t grow = (size_t)(b * Tt + kt * 64 + row) * Cc + h * Dd + c4;
            *(float4*)&KP[row * 68 + c4] = *(const float4*)&Km[grow];
            *(float4*)&Vs[row * 68 + c4] = *(const float4*)&Vm[grow];
        }
        __syncthreads();

        // S = Q . K^T  (4x4 per thread)
        float s[4][4] = {};
        #pragma unroll
        for (int d = 0; d < 64; d += 4) {
            float4 qa[4], kb[4];
            #pragma unroll
            for (int i = 0; i < 4; i++) qa[i] = *(const float4*)&Qs[(ty * 4 + i) * 64 + d];
            #pragma unroll
            for (int j = 0; j < 4; j++) kb[j] = *(const float4*)&KP[(tx * 4 + j) * 68 + d];
            #pragma unroll
            for (int i = 0; i < 4; i++)
                #pragma unroll
                for (int j = 0; j < 4; j++)
                    s[i][j] += qa[i].x * kb[j].x + qa[i].y * kb[j].y
                             + qa[i].z * kb[j].z + qa[i].w * kb[j].w;
        }

        // mask + interaction bias
        #pragma unroll
        for (int i = 0; i < 4; i++) {
            #pragma unroll
            for (int j = 0; j < 4; j++) {
                int kg = kt * 64 + tx * 4 + j;
                float val;
                if (kg > qg[i]) {
                    val = -INFINITY;
                } else {
                    float base = pm[i] ? s[i][j] * scale : -1e9f;
                    val = base + inter[(((size_t)b * Tt + kg) * Tt + qg[i]) * Hh + h];
                }
                s[i][j] = val;
            }
        }

        // online softmax update
        float alpha[4], rsum[4];
        #pragma unroll
        for (int i = 0; i < 4; i++) {
            float mloc = fmaxf(fmaxf(s[i][0], s[i][1]), fmaxf(s[i][2], s[i][3]));
            mloc = redmax16(mloc);
            float mnew = fmaxf(m_i[i], mloc);
            alpha[i] = __expf(m_i[i] - mnew);
            m_i[i] = mnew;
            float rs = 0.f;
            #pragma unroll
            for (int j = 0; j < 4; j++) {
                float p = __expf(s[i][j] - mnew);
                s[i][j] = p;
                rs += p;
            }
            rsum[i] = redsum16(rs);
            l_i[i] = l_i[i] * alpha[i] + rsum[i];
            #pragma unroll
            for (int j = 0; j < 4; j++) o[i][j] *= alpha[i];
        }

        __syncthreads();   // everyone done reading K from KP
        // store P into KP (P[q][k], stride 68)
        #pragma unroll
        for (int i = 0; i < 4; i++)
            #pragma unroll
            for (int j = 0; j < 4; j++)
                KP[(ty * 4 + i) * 68 + tx * 4 + j] = s[i][j];
        __syncthreads();

        // O += P @ V
        #pragma unroll 8
        for (int kk = 0; kk < 64; kk++) {
            float4 vv = *(const float4*)&Vs[kk * 68 + tx * 4];
            #pragma unroll
            for (int i = 0; i < 4; i++) {
                float pij = KP[(ty * 4 + i) * 68 + kk];
                o[i][0] += pij * vv.x;
                o[i][1] += pij * vv.y;
                o[i][2] += pij * vv.z;
                o[i][3] += pij * vv.w;
            }
        }
    }

    // epilogue: normalize and write ctx
    #pragma unroll
    for (int i = 0; i < 4; i++) {
        float inv = 1.f / l_i[i];
        float4 r;
        r.x = o[i][0] * inv; r.y = o[i][1] * inv;
        r.z = o[i][2] * inv; r.w = o[i][3] * inv;
        *(float4*)&ctx[(size_t)(b * Tt + qg[i]) * Cc + h * Dd + tx * 4] = r;
    }
}

// ---------------------------------------------------------------------------
extern "C" void kernel_launch(void* const* d_in, const int* in_sizes, int n_in,
                              void* d_out, int out_size)
{
    const float* x      = (const float*)d_in[0];
    const int*   pmask  = (const int*)  d_in[1];
    const float* inter  = (const float*)d_in[2];
    const float* W_ckv  = (const float*)d_in[3];
    const float* W_cq   = (const float*)d_in[4];
    const float* W_kc   = (const float*)d_in[5];
    const float* W_qc   = (const float*)d_in[6];
    const float* W_vc   = (const float*)d_in[7];
    const float* W_proj = (const float*)d_in[8];
    const float* b_proj = (const float*)d_in[9];
    float* out = (float*)d_out;

    float *kv_down, *q_down, *k, *q, *v, *ctx;
    cudaGetSymbolAddress((void**)&kv_down, g_kv_down);
    cudaGetSymbolAddress((void**)&q_down,  g_q_down);
    cudaGetSymbolAddress((void**)&k,       g_k);
    cudaGetSymbolAddress((void**)&q,       g_q);
    cudaGetSymbolAddress((void**)&v,       g_v);
    cudaGetSymbolAddress((void**)&ctx,     g_ctx);

    // down-projections: [4096,1024] @ [1024,256]
    dim3 gDown(Ll / 64, NROW / 64);
    sgemm64<<<gDown, 256>>>(x, W_ckv, kv_down, NROW, Ll, Cc, nullptr);
    sgemm64<<<gDown, 256>>>(x, W_cq,  q_down,  NROW, Ll, Cc, nullptr);

    // up-projections: [4096,256] @ [256,1024]
    dim3 gUp(Cc / 64, NROW / 64);
    sgemm64<<<gUp, 256>>>(kv_down, W_kc, k, NROW, Cc, Ll, nullptr);
    sgemm64<<<gUp, 256>>>(q_down,  W_qc, q, NROW, Cc, Ll, nullptr);
    sgemm64<<<gUp, 256>>>(kv_down, W_vc, v, NROW, Cc, Ll, nullptr);

    // fused attention
    size_t smem = (64 * 64 + 2 * 64 * 68) * sizeof(float);  // 51200 B
    cudaFuncSetAttribute(attn_kernel, cudaFuncAttributeMaxDynamicSharedMemorySize,
                         (int)smem);
    dim3 gAttn(Tt / 64, Hh, Bb);
    attn_kernel<<<gAttn, 256, smem>>>(q, k, v, inter, pmask, ctx);

    // output projection with bias: [4096,1024] @ [1024,1024] + b
    dim3 gProj(Cc / 64, NROW / 64);
    sgemm64<<<gProj, 256>>>(ctx, W_proj, out, NROW, Cc, Cc, b_proj);
}

// round 4
// speedup vs baseline: 1.7433x; 1.7433x over previous
#include <cuda_runtime.h>
#include <cuda_bf16.h>
#include <math.h>

// Problem constants
#define Bb 4
#define Tt 1024
#define Cc 1024
#define Hh 16
#define Ll 256
#define Dd 64
#define NROW (Bb*Tt)   // 4096

// Scratch (allocation-free: __device__ globals)
__device__ float g_kv_down[NROW * Ll];
__device__ float g_q_down [NROW * Ll];
__device__ float g_k  [NROW * Cc];
__device__ float g_q  [NROW * Cc];
__device__ float g_v  [NROW * Cc];
__device__ float g_ctx[NROW * Cc];
__device__ float g_biasT[(size_t)Bb * Hh * Tt * Tt];   // [b][h][q][k], 268MB

// ---------------------------------------------------------------------------
// SGEMM 64x64 tile, 4x4 microtile (used for N=256 down-projections)
// ---------------------------------------------------------------------------
__global__ __launch_bounds__(256) void sgemm64(
    const float* __restrict__ A, const float* __restrict__ B,
    float* __restrict__ C, int M, int N, int K,
    const float* __restrict__ bias)
{
    __shared__ float As[16][64];
    __shared__ float Bs[16][64];

    const int tid = threadIdx.x;
    const int tx = tid & 15;
    const int ty = tid >> 4;
    const int bm = blockIdx.y * 64;
    const int bn = blockIdx.x * 64;

    float acc[4][4] = {};

    for (int k0 = 0; k0 < K; k0 += 16) {
        {
            int row = tid >> 2;
            int c4  = (tid & 3) * 4;
            float4 a = *(const float4*)&A[(size_t)(bm + row) * K + k0 + c4];
            As[c4 + 0][row] = a.x;
            As[c4 + 1][row] = a.y;
            As[c4 + 2][row] = a.z;
            As[c4 + 3][row] = a.w;
        }
        {
            int row = tid >> 4;
            int c4  = (tid & 15) * 4;
            *(float4*)&Bs[row][c4] = *(const float4*)&B[(size_t)(k0 + row) * N + bn + c4];
        }
        __syncthreads();

        #pragma unroll
        for (int kk = 0; kk < 16; kk++) {
            float4 a = *(const float4*)&As[kk][ty * 4];
            float4 b = *(const float4*)&Bs[kk][tx * 4];
            float ar[4] = {a.x, a.y, a.z, a.w};
            float br[4] = {b.x, b.y, b.z, b.w};
            #pragma unroll
            for (int i = 0; i < 4; i++)
                #pragma unroll
                for (int j = 0; j < 4; j++)
                    acc[i][j] += ar[i] * br[j];
        }
        __syncthreads();
    }

    float4 bv = {0.f, 0.f, 0.f, 0.f};
    if (bias) bv = *(const float4*)&bias[bn + tx * 4];
    #pragma unroll
    for (int i = 0; i < 4; i++) {
        float4 r;
        r.x = acc[i][0] + bv.x;
        r.y = acc[i][1] + bv.y;
        r.z = acc[i][2] + bv.z;
        r.w = acc[i][3] + bv.w;
        *(float4*)&C[(size_t)(bm + ty * 4 + i) * N + bn + tx * 4] = r;
    }
}

// ---------------------------------------------------------------------------
// SGEMM 128x128 tile, 8x8 microtile, 256 threads (LDS/FMA balanced)
// Requires M%128==0, N%128==0, K%16==0.
// ---------------------------------------------------------------------------
__global__ __launch_bounds__(256) void sgemm128(
    const float* __restrict__ A, const float* __restrict__ B,
    float* __restrict__ C, int M, int N, int K,
    const float* __restrict__ bias)
{
    __shared__ float As[16][128];
    __shared__ float Bs[16][128];

    const int tid = threadIdx.x;
    const int tx = tid & 15;       // 8 N-cols each
    const int ty = tid >> 4;       // 8 M-rows each
    const int bm = blockIdx.y * 128;
    const int bn = blockIdx.x * 128;

    float acc[8][8] = {};

    for (int k0 = 0; k0 < K; k0 += 16) {
        // A tile: 128 rows x 16 cols, store transposed As[k][m]
        {
            int row = tid >> 1;            // 0..127
            int cb  = (tid & 1) * 8;       // 0 or 8
            float4 a0 = *(const float4*)&A[(size_t)(bm + row) * K + k0 + cb];
            float4 a1 = *(const float4*)&A[(size_t)(bm + row) * K + k0 + cb + 4];
            As[cb + 0][row] = a0.x; As[cb + 1][row] = a0.y;
            As[cb + 2][row] = a0.z; As[cb + 3][row] = a0.w;
            As[cb + 4][row] = a1.x; As[cb + 5][row] = a1.y;
            As[cb + 6][row] = a1.z; As[cb + 7][row] = a1.w;
        }
        // B tile: 16 rows x 128 cols
        {
            int row = tid >> 4;            // 0..15
            int cb  = (tid & 15) * 8;
            *(float4*)&Bs[row][cb]     = *(const float4*)&B[(size_t)(k0 + row) * N + bn + cb];
            *(float4*)&Bs[row][cb + 4] = *(const float4*)&B[(size_t)(k0 + row) * N + bn + cb + 4];
        }
        __syncthreads();

        #pragma unroll
        for (int kk = 0; kk < 16; kk++) {
            float ar[8], br[8];
            *(float4*)&ar[0] = *(const float4*)&As[kk][ty * 8];
            *(float4*)&ar[4] = *(const float4*)&As[kk][ty * 8 + 4];
            *(float4*)&br[0] = *(const float4*)&Bs[kk][tx * 8];
            *(float4*)&br[4] = *(const float4*)&Bs[kk][tx * 8 + 4];
            #pragma unroll
            for (int i = 0; i < 8; i++)
                #pragma unroll
                for (int j = 0; j < 8; j++)
                    acc[i][j] += ar[i] * br[j];
        }
        __syncthreads();
    }

    float bv[8] = {};
    if (bias) {
        *(float4*)&bv[0] = *(const float4*)&bias[bn + tx * 8];
        *(float4*)&bv[4] = *(const float4*)&bias[bn + tx * 8 + 4];
    }
    #pragma unroll
    for (int i = 0; i < 8; i++) {
        float4 r0, r1;
        r0.x = acc[i][0] + bv[0]; r0.y = acc[i][1] + bv[1];
        r0.z = acc[i][2] + bv[2]; r0.w = acc[i][3] + bv[3];
        r1.x = acc[i][4] + bv[4]; r1.y = acc[i][5] + bv[5];
        r1.z = acc[i][6] + bv[6]; r1.w = acc[i][7] + bv[7];
        float* crow = &C[(size_t)(bm + ty * 8 + i) * N + bn + tx * 8];
        *(float4*)&crow[0] = r0;
        *(float4*)&crow[4] = r1;
    }
}

// ---------------------------------------------------------------------------
// Transpose interaction matrix: in[b][k][q][h] -> out[b][h][q][k]
// Block: 32 k x 8 q x all 16 h. Both phases fully coalesced; smem stride 129
// keeps the shuffle conflict-free.
// ---------------------------------------------------------------------------
__global__ __launch_bounds__(256) void transpose_bias(
    const float* __restrict__ in, float* __restrict__ out)
{
    __shared__ float tile[32 * 129];
    const int k0 = blockIdx.x * 32;
    const int q0 = blockIdx.y * 8;
    const int b  = blockIdx.z;

    const size_t ibase = ((size_t)(b * Tt + k0) * Tt + q0) * Hh;
    #pragma unroll
    for (int it = 0; it < 16; it++) {
        int t  = it * 256 + threadIdx.x;
        int kk = t >> 7;          // 0..31
        int r  = t & 127;         // qq*16 + h, contiguous in gmem
        tile[kk * 129 + r] = in[ibase + (size_t)kk * (Tt * Hh) + r];
    }
    __syncthreads();
    #pragma unroll
    for (int it = 0; it < 16; it++) {
        int t  = it * 256 + threadIdx.x;
        int kk = t & 31;
        int o  = t >> 5;          // h*8 + qq
        int h  = o >> 3;
        int qq = o & 7;
        out[((size_t)(b * Hh + h) * Tt + q0 + qq) * Tt + k0 + kk] =
            tile[kk * 129 + qq * 16 + h];
    }
}

// ---------------------------------------------------------------------------
// Fused flash attention; bias now read coalesced from biasT[b][h][q][k].
// ---------------------------------------------------------------------------
__device__ __forceinline__ float redmax16(float v) {
    #pragma unroll
    for (int m = 8; m >= 1; m >>= 1)
        v = fmaxf(v, __shfl_xor_sync(0xffffffffu, v, m));
    return v;
}
__device__ __forceinline__ float redsum16(float v) {
    #pragma unroll
    for (int m = 8; m >= 1; m >>= 1)
        v += __shfl_xor_sync(0xffffffffu, v, m);
    return v;
}

__global__ __launch_bounds__(256) void attn_kernel(
    const float* __restrict__ Qm, const float* __restrict__ Km,
    const float* __restrict__ Vm, const float* __restrict__ biasT,
    const int* __restrict__ pad, float* __restrict__ ctx)
{
    extern __shared__ float sm[];
    float* Qs = sm;                  // [64][64]
    float* KP = sm + 64 * 64;        // [64][68]  K tile, reused as P
    float* Vs = KP + 64 * 68;        // [64][68]

    const int qt = blockIdx.x;
    const int h  = blockIdx.y;
    const int b  = blockIdx.z;
    const int tid = threadIdx.x;
    const int tx = tid & 15;
    const int ty = tid >> 4;
    const float scale = 0.125f;

    const float* bias_bh = biasT + (size_t)(b * Hh + h) * Tt * Tt;

    for (int i = tid; i < 64 * 16; i += 256) {
        int row = i >> 4, c4 = (i & 15) * 4;
        *(float4*)&Qs[row * 64 + c4] =
            *(const float4*)&Qm[(size_t)(b * Tt + qt * 64 + row) * Cc + h * Dd + c4];
    }

    float m_i[4], l_i[4], o[4][4];
    int qg[4], pm[4];
    #pragma unroll
    for (int i = 0; i < 4; i++) {
        m_i[i] = -INFINITY; l_i[i] = 0.f;
        qg[i] = qt * 64 + ty * 4 + i;
        pm[i] = pad[b * Tt + qg[i]];
        #pragma unroll
        for (int j = 0; j < 4; j++) o[i][j] = 0.f;
    }

    for (int kt = 0; kt <= qt; kt++) {
        __syncthreads();
        for (int i = tid; i < 64 * 16; i += 256) {
            int row = i >> 4, c4 = (i & 15) * 4;
            size_t grow = (size_t)(b * Tt + kt * 64 + row) * Cc + h * Dd + c4;
            *(float4*)&KP[row * 68 + c4] = *(const float4*)&Km[grow];
            *(float4*)&Vs[row * 68 + c4] = *(const float4*)&Vm[grow];
        }
        __syncthreads();

        // S = Q . K^T
        float s[4][4] = {};
        #pragma unroll
        for (int d = 0; d < 64; d += 4) {
            float4 qa[4], kb[4];
            #pragma unroll
            for (int i = 0; i < 4; i++) qa[i] = *(const float4*)&Qs[(ty * 4 + i) * 64 + d];
            #pragma unroll
            for (int j = 0; j < 4; j++) kb[j] = *(const float4*)&KP[(tx * 4 + j) * 68 + d];
            #pragma unroll
            for (int i = 0; i < 4; i++)
                #pragma unroll
                for (int j = 0; j < 4; j++)
                    s[i][j] += qa[i].x * kb[j].x + qa[i].y * kb[j].y
                             + qa[i].z * kb[j].z + qa[i].w * kb[j].w;
        }

        // mask + interaction bias (coalesced float4 from biasT)
        #pragma unroll
        for (int i = 0; i < 4; i++) {
            float4 bi = *(const float4*)&bias_bh[(size_t)qg[i] * Tt + kt * 64 + tx * 4];
            float br[4] = {bi.x, bi.y, bi.z, bi.w};
            #pragma unroll
            for (int j = 0; j < 4; j++) {
                int kg = kt * 64 + tx * 4 + j;
                float val;
                if (kg > qg[i]) {
                    val = -INFINITY;
                } else {
                    float base = pm[i] ? s[i][j] * scale : -1e9f;
                    val = base + br[j];
                }
                s[i][j] = val;
            }
        }

        // online softmax update
        float alpha[4];
        #pragma unroll
        for (int i = 0; i < 4; i++) {
            float mloc = fmaxf(fmaxf(s[i][0], s[i][1]), fmaxf(s[i][2], s[i][3]));
            mloc = redmax16(mloc);
            float mnew = fmaxf(m_i[i], mloc);
            alpha[i] = __expf(m_i[i] - mnew);
            m_i[i] = mnew;
            float rs = 0.f;
            #pragma unroll
            for (int j = 0; j < 4; j++) {
                float p = __expf(s[i][j] - mnew);
                s[i][j] = p;
                rs += p;
            }
            rs = redsum16(rs);
            l_i[i] = l_i[i] * alpha[i] + rs;
            #pragma unroll
            for (int j = 0; j < 4; j++) o[i][j] *= alpha[i];
        }

        __syncthreads();
        #pragma unroll
        for (int i = 0; i < 4; i++)
            #pragma unroll
            for (int j = 0; j < 4; j++)
                KP[(ty * 4 + i) * 68 + tx * 4 + j] = s[i][j];
        __syncthreads();

        // O += P @ V
        #pragma unroll 8
        for (int kk = 0; kk < 64; kk++) {
            float4 vv = *(const float4*)&Vs[kk * 68 + tx * 4];
            #pragma unroll
            for (int i = 0; i < 4; i++) {
                float pij = KP[(ty * 4 + i) * 68 + kk];
                o[i][0] += pij * vv.x;
                o[i][1] += pij * vv.y;
                o[i][2] += pij * vv.z;
                o[i][3] += pij * vv.w;
            }
        }
    }

    #pragma unroll
    for (int i = 0; i < 4; i++) {
        float inv = 1.f / l_i[i];
        float4 r;
        r.x = o[i][0] * inv; r.y = o[i][1] * inv;
        r.z = o[i][2] * inv; r.w = o[i][3] * inv;
        *(float4*)&ctx[(size_t)(b * Tt + qg[i]) * Cc + h * Dd + tx * 4] = r;
    }
}

// ---------------------------------------------------------------------------
extern "C" void kernel_launch(void* const* d_in, const int* in_sizes, int n_in,
                              void* d_out, int out_size)
{
    const float* x      = (const float*)d_in[0];
    const int*   pmask  = (const int*)  d_in[1];
    const float* inter  = (const float*)d_in[2];
    const float* W_ckv  = (const float*)d_in[3];
    const float* W_cq   = (const float*)d_in[4];
    const float* W_kc   = (const float*)d_in[5];
    const float* W_qc   = (const float*)d_in[6];
    const float* W_vc   = (const float*)d_in[7];
    const float* W_proj = (const float*)d_in[8];
    const float* b_proj = (const float*)d_in[9];
    float* out = (float*)d_out;

    float *kv_down, *q_down, *k, *q, *v, *ctx, *biasT;
    cudaGetSymbolAddress((void**)&kv_down, g_kv_down);
    cudaGetSymbolAddress((void**)&q_down,  g_q_down);
    cudaGetSymbolAddress((void**)&k,       g_k);
    cudaGetSymbolAddress((void**)&q,       g_q);
    cudaGetSymbolAddress((void**)&v,       g_v);
    cudaGetSymbolAddress((void**)&ctx,     g_ctx);
    cudaGetSymbolAddress((void**)&biasT,   g_biasT);

    // transpose interaction matrix first (independent of GEMMs)
    dim3 gT(Tt / 32, Tt / 8, Bb);
    transpose_bias<<<gT, 256>>>(inter, biasT);

    // down-projections: [4096,1024] @ [1024,256]
    dim3 gDown(Ll / 64, NROW / 64);
    sgemm64<<<gDown, 256>>>(x, W_ckv, kv_down, NROW, Ll, Cc, nullptr);
    sgemm64<<<gDown, 256>>>(x, W_cq,  q_down,  NROW, Ll, Cc, nullptr);

    // up-projections: [4096,256] @ [256,1024]
    dim3 gUp(Cc / 128, NROW / 128);
    sgemm128<<<gUp, 256>>>(kv_down, W_kc, k, NROW, Cc, Ll, nullptr);
    sgemm128<<<gUp, 256>>>(q_down,  W_qc, q, NROW, Cc, Ll, nullptr);
    sgemm128<<<gUp, 256>>>(kv_down, W_vc, v, NROW, Cc, Ll, nullptr);

    // fused attention
    size_t smem = (64 * 64 + 2 * 64 * 68) * sizeof(float);  // 51200 B
    cudaFuncSetAttribute(attn_kernel, cudaFuncAttributeMaxDynamicSharedMemorySize,
                         (int)smem);
    dim3 gAttn(Tt / 64, Hh, Bb);
    attn_kernel<<<gAttn, 256, smem>>>(q, k, v, biasT, pmask, ctx);

    // output projection with bias
    dim3 gProj(Cc / 128, NROW / 128);
    sgemm128<<<gProj, 256>>>(ctx, W_proj, out, NROW, Cc, Cc, b_proj);
}

// round 5
// speedup vs baseline: 2.5853x; 1.4830x over previous
#include <cuda_runtime.h>
#include <cuda_bf16.h>
#include <math.h>
#include <stdint.h>

// Problem constants
#define Bb 4
#define Tt 1024
#define Cc 1024
#define Hh 16
#define Ll 256
#define Dd 64
#define NROW (Bb*Tt)   // 4096

// Scratch (allocation-free: __device__ globals)
__device__ float g_kv_down[NROW * Ll];
__device__ float g_q_down [NROW * Ll];
__device__ float g_k  [NROW * Cc];
__device__ float g_q  [NROW * Cc];
__device__ float g_v  [NROW * Cc];
__device__ float g_ctx[NROW * Cc];
__device__ float g_biasT[(size_t)Bb * Hh * Tt * Tt];   // [b][h][q][k], 268MB

// ---------------------------------------------------------------------------
// SGEMM 64x64 tile, 4x4 microtile (N=256 down-projections)
// ---------------------------------------------------------------------------
__global__ __launch_bounds__(256) void sgemm64(
    const float* __restrict__ A, const float* __restrict__ B,
    float* __restrict__ C, int M, int N, int K,
    const float* __restrict__ bias)
{
    __shared__ float As[16][64];
    __shared__ float Bs[16][64];

    const int tid = threadIdx.x;
    const int tx = tid & 15;
    const int ty = tid >> 4;
    const int bm = blockIdx.y * 64;
    const int bn = blockIdx.x * 64;

    float acc[4][4] = {};

    for (int k0 = 0; k0 < K; k0 += 16) {
        {
            int row = tid >> 2;
            int c4  = (tid & 3) * 4;
            float4 a = *(const float4*)&A[(size_t)(bm + row) * K + k0 + c4];
            As[c4 + 0][row] = a.x;
            As[c4 + 1][row] = a.y;
            As[c4 + 2][row] = a.z;
            As[c4 + 3][row] = a.w;
        }
        {
            int row = tid >> 4;
            int c4  = (tid & 15) * 4;
            *(float4*)&Bs[row][c4] = *(const float4*)&B[(size_t)(k0 + row) * N + bn + c4];
        }
        __syncthreads();

        #pragma unroll
        for (int kk = 0; kk < 16; kk++) {
            float4 a = *(const float4*)&As[kk][ty * 4];
            float4 b = *(const float4*)&Bs[kk][tx * 4];
            float ar[4] = {a.x, a.y, a.z, a.w};
            float br[4] = {b.x, b.y, b.z, b.w};
            #pragma unroll
            for (int i = 0; i < 4; i++)
                #pragma unroll
                for (int j = 0; j < 4; j++)
                    acc[i][j] += ar[i] * br[j];
        }
        __syncthreads();
    }

    float4 bv = {0.f, 0.f, 0.f, 0.f};
    if (bias) bv = *(const float4*)&bias[bn + tx * 4];
    #pragma unroll
    for (int i = 0; i < 4; i++) {
        float4 r;
        r.x = acc[i][0] + bv.x;
        r.y = acc[i][1] + bv.y;
        r.z = acc[i][2] + bv.z;
        r.w = acc[i][3] + bv.w;
        *(float4*)&C[(size_t)(bm + ty * 4 + i) * N + bn + tx * 4] = r;
    }
}

// ---------------------------------------------------------------------------
// SGEMM 128x128 tile, 8x8 microtile, 256 threads
// ---------------------------------------------------------------------------
__global__ __launch_bounds__(256) void sgemm128(
    const float* __restrict__ A, const float* __restrict__ B,
    float* __restrict__ C, int M, int N, int K,
    const float* __restrict__ bias)
{
    __shared__ float As[16][128];
    __shared__ float Bs[16][128];

    const int tid = threadIdx.x;
    const int tx = tid & 15;
    const int ty = tid >> 4;
    const int bm = blockIdx.y * 128;
    const int bn = blockIdx.x * 128;

    float acc[8][8] = {};

    for (int k0 = 0; k0 < K; k0 += 16) {
        {
            int row = tid >> 1;
            int cb  = (tid & 1) * 8;
            float4 a0 = *(const float4*)&A[(size_t)(bm + row) * K + k0 + cb];
            float4 a1 = *(const float4*)&A[(size_t)(bm + row) * K + k0 + cb + 4];
            As[cb + 0][row] = a0.x; As[cb + 1][row] = a0.y;
            As[cb + 2][row] = a0.z; As[cb + 3][row] = a0.w;
            As[cb + 4][row] = a1.x; As[cb + 5][row] = a1.y;
            As[cb + 6][row] = a1.z; As[cb + 7][row] = a1.w;
        }
        {
            int row = tid >> 4;
            int cb  = (tid & 15) * 8;
            *(float4*)&Bs[row][cb]     = *(const float4*)&B[(size_t)(k0 + row) * N + bn + cb];
            *(float4*)&Bs[row][cb + 4] = *(const float4*)&B[(size_t)(k0 + row) * N + bn + cb + 4];
        }
        __syncthreads();

        #pragma unroll
        for (int kk = 0; kk < 16; kk++) {
            float ar[8], br[8];
            *(float4*)&ar[0] = *(const float4*)&As[kk][ty * 8];
            *(float4*)&ar[4] = *(const float4*)&As[kk][ty * 8 + 4];
            *(float4*)&br[0] = *(const float4*)&Bs[kk][tx * 8];
            *(float4*)&br[4] = *(const float4*)&Bs[kk][tx * 8 + 4];
            #pragma unroll
            for (int i = 0; i < 8; i++)
                #pragma unroll
                for (int j = 0; j < 8; j++)
                    acc[i][j] += ar[i] * br[j];
        }
        __syncthreads();
    }

    float bv[8] = {};
    if (bias) {
        *(float4*)&bv[0] = *(const float4*)&bias[bn + tx * 8];
        *(float4*)&bv[4] = *(const float4*)&bias[bn + tx * 8 + 4];
    }
    #pragma unroll
    for (int i = 0; i < 8; i++) {
        float4 r0, r1;
        r0.x = acc[i][0] + bv[0]; r0.y = acc[i][1] + bv[1];
        r0.z = acc[i][2] + bv[2]; r0.w = acc[i][3] + bv[3];
        r1.x = acc[i][4] + bv[4]; r1.y = acc[i][5] + bv[5];
        r1.z = acc[i][6] + bv[6]; r1.w = acc[i][7] + bv[7];
        float* crow = &C[(size_t)(bm + ty * 8 + i) * N + bn + tx * 8];
        *(float4*)&crow[0] = r0;
        *(float4*)&crow[4] = r1;
    }
}

// ---------------------------------------------------------------------------
// Transpose interaction matrix: in[b][k][q][h] -> out[b][h][q][k]
// ---------------------------------------------------------------------------
__global__ __launch_bounds__(256) void transpose_bias(
    const float* __restrict__ in, float* __restrict__ out)
{
    __shared__ float tile[32 * 129];
    const int k0 = blockIdx.x * 32;
    const int q0 = blockIdx.y * 8;
    const int b  = blockIdx.z;

    const size_t ibase = ((size_t)(b * Tt + k0) * Tt + q0) * Hh;
    #pragma unroll
    for (int it = 0; it < 16; it++) {
        int t  = it * 256 + threadIdx.x;
        int kk = t >> 7;
        int r  = t & 127;
        tile[kk * 129 + r] = in[ibase + (size_t)kk * (Tt * Hh) + r];
    }
    __syncthreads();
    #pragma unroll
    for (int it = 0; it < 16; it++) {
        int t  = it * 256 + threadIdx.x;
        int kk = t & 31;
        int o  = t >> 5;
        int h  = o >> 3;
        int qq = o & 7;
        out[((size_t)(b * Hh + h) * Tt + q0 + qq) * Tt + k0 + kk] =
            tile[kk * 129 + qq * 16 + h];
    }
}

// ---------------------------------------------------------------------------
// Tensor-core flash attention (tf32 mma.sync.m16n8k8).
// Block = 128 threads (4 warps); tile 64 q x 64 k; warp w owns q rows
// [w*16, w*16+16). Smem strides: Q/K/P = 68 (conflict-free g*4+tig),
// V = 72 (conflict-free tig*8+g).
// ---------------------------------------------------------------------------
#define QS 68
#define KS 68
#define VS 72

__device__ __forceinline__ float ftf32(float x) {
    float r;
    asm("cvt.rna.tf32.f32 %0, %1;" : "=f"(r) : "f"(x));
    return r;
}

__device__ __forceinline__ void mma_tf32(
    float& c0, float& c1, float& c2, float& c3,
    float a0, float a1, float a2, float a3,
    float b0, float b1)
{
    asm volatile(
        "mma.sync.aligned.m16n8k8.row.col.f32.tf32.tf32.f32 "
        "{%0,%1,%2,%3},{%4,%5,%6,%7},{%8,%9},{%0,%1,%2,%3};\n"
        : "+f"(c0), "+f"(c1), "+f"(c2), "+f"(c3)
        : "r"(__float_as_uint(a0)), "r"(__float_as_uint(a1)),
          "r"(__float_as_uint(a2)), "r"(__float_as_uint(a3)),
          "r"(__float_as_uint(b0)), "r"(__float_as_uint(b1)));
}

__global__ __launch_bounds__(128) void attn_tc(
    const float* __restrict__ Qm, const float* __restrict__ Km,
    const float* __restrict__ Vm, const float* __restrict__ biasT,
    const int* __restrict__ pad, float* __restrict__ ctx)
{
    extern __shared__ float sm[];
    float* Qs = sm;               // [64][QS]
    float* KP = Qs + 64 * QS;     // [64][KS] : K tile, reused as P
    float* Vs = KP + 64 * KS;     // [64][VS]

    const int qt = blockIdx.x;
    const int h  = blockIdx.y;
    const int b  = blockIdx.z;
    const int tid  = threadIdx.x;
    const int warp = tid >> 5;
    const int lane = tid & 31;
    const int g    = lane >> 2;     // 0..7
    const int tig  = lane & 3;      // 0..3

    const int qrow0 = warp * 16 + g;       // local q rows (c0/c1)
    const int qg0 = qt * 64 + qrow0;       // global
    const int qg1 = qg0 + 8;

    const float* bias_bh = biasT + (size_t)(b * Hh + h) * Tt * Tt;
    const int pm0 = pad[b * Tt + qg0];
    const int pm1 = pad[b * Tt + qg1];

    // load Q tile, fold softmax scale, convert tf32
    for (int i = tid; i < 64 * 16; i += 128) {
        int row = i >> 4, c4 = (i & 15) * 4;
        float4 qv = *(const float4*)&Qm[(size_t)(b * Tt + qt * 64 + row) * Cc + h * Dd + c4];
        Qs[row * QS + c4 + 0] = ftf32(qv.x * 0.125f);
        Qs[row * QS + c4 + 1] = ftf32(qv.y * 0.125f);
        Qs[row * QS + c4 + 2] = ftf32(qv.z * 0.125f);
        Qs[row * QS + c4 + 3] = ftf32(qv.w * 0.125f);
    }

    float m0 = -INFINITY, m1 = -INFINITY, l0 = 0.f, l1 = 0.f;
    float o[8][4];
    #pragma unroll
    for (int n = 0; n < 8; n++)
        #pragma unroll
        for (int j = 0; j < 4; j++) o[n][j] = 0.f;

    for (int kt = 0; kt <= qt; kt++) {
        __syncthreads();   // prev iter done with KP(P)/Vs; Q load done (iter 0)
        for (int i = tid; i < 64 * 16; i += 128) {
            int row = i >> 4, c4 = (i & 15) * 4;
            size_t grow = (size_t)(b * Tt + kt * 64 + row) * Cc + h * Dd + c4;
            float4 kv = *(const float4*)&Km[grow];
            float4 vv = *(const float4*)&Vm[grow];
            KP[row * KS + c4 + 0] = ftf32(kv.x);
            KP[row * KS + c4 + 1] = ftf32(kv.y);
            KP[row * KS + c4 + 2] = ftf32(kv.z);
            KP[row * KS + c4 + 3] = ftf32(kv.w);
            Vs[row * VS + c4 + 0] = ftf32(vv.x);
            Vs[row * VS + c4 + 1] = ftf32(vv.y);
            Vs[row * VS + c4 + 2] = ftf32(vv.z);
            Vs[row * VS + c4 + 3] = ftf32(vv.w);
        }
        __syncthreads();

        // ---- S = Q @ K^T : 8 n-tiles of m16n8, k over 8 chunks ----
        float s[8][4];
        #pragma unroll
        for (int n = 0; n < 8; n++)
            #pragma unroll
            for (int j = 0; j < 4; j++) s[n][j] = 0.f;

        #pragma unroll
        for (int kc = 0; kc < 64; kc += 8) {
            float a0 = Qs[(warp * 16 + g)     * QS + kc + tig];
            float a1 = Qs[(warp * 16 + g + 8) * QS + kc + tig];
            float a2 = Qs[(warp * 16 + g)     * QS + kc + tig + 4];
            float a3 = Qs[(warp * 16 + g + 8) * QS + kc + tig + 4];
            #pragma unroll
            for (int n = 0; n < 8; n++) {
                float b0 = KP[(n * 8 + g) * KS + kc + tig];
                float b1 = KP[(n * 8 + g) * KS + kc + tig + 4];
                mma_tf32(s[n][0], s[n][1], s[n][2], s[n][3], a0, a1, a2, a3, b0, b1);
            }
        }

        // ---- mask + bias ----
        const int kbase = kt * 64;
        const bool diag = (kt == qt);
        #pragma unroll
        for (int n = 0; n < 8; n++) {
            int kg = kbase + n * 8 + 2 * tig;
            float2 bi0 = *(const float2*)&bias_bh[(size_t)qg0 * Tt + kg];
            float2 bi1 = *(const float2*)&bias_bh[(size_t)qg1 * Tt + kg];
            s[n][0] = (pm0 ? s[n][0] : -1e9f) + bi0.x;
            s[n][1] = (pm0 ? s[n][1] : -1e9f) + bi0.y;
            s[n][2] = (pm1 ? s[n][2] : -1e9f) + bi1.x;
            s[n][3] = (pm1 ? s[n][3] : -1e9f) + bi1.y;
            if (diag) {
                if (kg     > qg0) s[n][0] = -INFINITY;
                if (kg + 1 > qg0) s[n][1] = -INFINITY;
                if (kg     > qg1) s[n][2] = -INFINITY;
                if (kg + 1 > qg1) s[n][3] = -INFINITY;
            }
        }

        // ---- online softmax (quad reduce over lanes xor 1,2) ----
        float rm0 = -INFINITY, rm1 = -INFINITY;
        #pragma unroll
        for (int n = 0; n < 8; n++) {
            rm0 = fmaxf(rm0, fmaxf(s[n][0], s[n][1]));
            rm1 = fmaxf(rm1, fmaxf(s[n][2], s[n][3]));
        }
        rm0 = fmaxf(rm0, __shfl_xor_sync(0xffffffffu, rm0, 1));
        rm0 = fmaxf(rm0, __shfl_xor_sync(0xffffffffu, rm0, 2));
        rm1 = fmaxf(rm1, __shfl_xor_sync(0xffffffffu, rm1, 1));
        rm1 = fmaxf(rm1, __shfl_xor_sync(0xffffffffu, rm1, 2));

        float mn0 = fmaxf(m0, rm0);
        float mn1 = fmaxf(m1, rm1);
        float al0 = __expf(m0 - mn0);
        float al1 = __expf(m1 - mn1);
        m0 = mn0; m1 = mn1;

        float rs0 = 0.f, rs1 = 0.f;
        #pragma unroll
        for (int n = 0; n < 8; n++) {
            s[n][0] = __expf(s[n][0] - mn0);
            s[n][1] = __expf(s[n][1] - mn0);
            s[n][2] = __expf(s[n][2] - mn1);
            s[n][3] = __expf(s[n][3] - mn1);
            rs0 += s[n][0] + s[n][1];
            rs1 += s[n][2] + s[n][3];
        }
        rs0 += __shfl_xor_sync(0xffffffffu, rs0, 1);
        rs0 += __shfl_xor_sync(0xffffffffu, rs0, 2);
        rs1 += __shfl_xor_sync(0xffffffffu, rs1, 1);
        rs1 += __shfl_xor_sync(0xffffffffu, rs1, 2);
        l0 = l0 * al0 + rs0;
        l1 = l1 * al1 + rs1;

        #pragma unroll
        for (int n = 0; n < 8; n++) {
            o[n][0] *= al0; o[n][1] *= al0;
            o[n][2] *= al1; o[n][3] *= al1;
        }

        __syncthreads();   // all warps done reading K from KP
        // store P (tf32) into KP
        #pragma unroll
        for (int n = 0; n < 8; n++) {
            KP[(warp * 16 + g)     * KS + n * 8 + 2 * tig]     = ftf32(s[n][0]);
            KP[(warp * 16 + g)     * KS + n * 8 + 2 * tig + 1] = ftf32(s[n][1]);
            KP[(warp * 16 + g + 8) * KS + n * 8 + 2 * tig]     = ftf32(s[n][2]);
            KP[(warp * 16 + g + 8) * KS + n * 8 + 2 * tig + 1] = ftf32(s[n][3]);
        }
        __syncthreads();

        // ---- O += P @ V ----
        #pragma unroll
        for (int kc = 0; kc < 64; kc += 8) {
            float a0 = KP[(warp * 16 + g)     * KS + kc + tig];
            float a1 = KP[(warp * 16 + g + 8) * KS + kc + tig];
            float a2 = KP[(warp * 16 + g)     * KS + kc + tig + 4];
            float a3 = KP[(warp * 16 + g + 8) * KS + kc + tig + 4];
            #pragma unroll
            for (int n = 0; n < 8; n++) {
                float b0 = Vs[(kc + tig)     * VS + n * 8 + g];
                float b1 = Vs[(kc + tig + 4) * VS + n * 8 + g];
                mma_tf32(o[n][0], o[n][1], o[n][2], o[n][3], a0, a1, a2, a3, b0, b1);
            }
        }
    }

    // epilogue
    float inv0 = 1.f / l0;
    float inv1 = 1.f / l1;
    #pragma unroll
    for (int n = 0; n < 8; n++) {
        int d = n * 8 + 2 * tig;
        float2 r0 = {o[n][0] * inv0, o[n][1] * inv0};
        float2 r1 = {o[n][2] * inv1, o[n][3] * inv1};
        *(float2*)&ctx[(size_t)(b * Tt + qg0) * Cc + h * Dd + d] = r0;
        *(float2*)&ctx[(size_t)(b * Tt + qg1) * Cc + h * Dd + d] = r1;
    }
}

// ---------------------------------------------------------------------------
extern "C" void kernel_launch(void* const* d_in, const int* in_sizes, int n_in,
                              void* d_out, int out_size)
{
    const float* x      = (const float*)d_in[0];
    const int*   pmask  = (const int*)  d_in[1];
    const float* inter  = (const float*)d_in[2];
    const float* W_ckv  = (const float*)d_in[3];
    const float* W_cq   = (const float*)d_in[4];
    const float* W_kc   = (const float*)d_in[5];
    const float* W_qc   = (const float*)d_in[6];
    const float* W_vc   = (const float*)d_in[7];
    const float* W_proj = (const float*)d_in[8];
    const float* b_proj = (const float*)d_in[9];
    float* out = (float*)d_out;

    float *kv_down, *q_down, *k, *q, *v, *ctx, *biasT;
    cudaGetSymbolAddress((void**)&kv_down, g_kv_down);
    cudaGetSymbolAddress((void**)&q_down,  g_q_down);
    cudaGetSymbolAddress((void**)&k,       g_k);
    cudaGetSymbolAddress((void**)&q,       g_q);
    cudaGetSymbolAddress((void**)&v,       g_v);
    cudaGetSymbolAddress((void**)&ctx,     g_ctx);
    cudaGetSymbolAddress((void**)&biasT,   g_biasT);

    // transpose interaction matrix (independent of GEMM chain)
    dim3 gT(Tt / 32, Tt / 8, Bb);
    transpose_bias<<<gT, 256>>>(inter, biasT);

    // down-projections: [4096,1024] @ [1024,256]
    dim3 gDown(Ll / 64, NROW / 64);
    sgemm64<<<gDown, 256>>>(x, W_ckv, kv_down, NROW, Ll, Cc, nullptr);
    sgemm64<<<gDown, 256>>>(x, W_cq,  q_down,  NROW, Ll, Cc, nullptr);

    // up-projections: [4096,256] @ [256,1024]
    dim3 gUp(Cc / 128, NROW / 128);
    sgemm128<<<gUp, 256>>>(kv_down, W_kc, k, NROW, Cc, Ll, nullptr);
    sgemm128<<<gUp, 256>>>(q_down,  W_qc, q, NROW, Cc, Ll, nullptr);
    sgemm128<<<gUp, 256>>>(kv_down, W_vc, v, NROW, Cc, Ll, nullptr);

    // tensor-core flash attention
    size_t smem = (64 * QS + 64 * KS + 64 * VS) * sizeof(float);  // 53248 B
    cudaFuncSetAttribute(attn_tc, cudaFuncAttributeMaxDynamicSharedMemorySize,
                         (int)smem);
    dim3 gAttn(Tt / 64, Hh, Bb);
    attn_tc<<<gAttn, 128, smem>>>(q, k, v, biasT, pmask, ctx);

    // output projection with bias
    dim3 gProj(Cc / 128, NROW / 128);
    sgemm128<<<gProj, 256>>>(ctx, W_proj, out, NROW, Cc, Cc, b_proj);
}

// round 9
// speedup vs baseline: 4.1646x; 1.6109x over previous
#include <cuda_runtime.h>
#include <cuda_bf16.h>
#include <math.h>
#include <stdint.h>

// Problem constants
#define Bb 4
#define Tt 1024
#define Cc 1024
#define Hh 16
#define Ll 256
#define Dd 64
#define NROW (Bb*Tt)   // 4096

// Scratch (allocation-free: __device__ globals)
__device__ float g_kv_down[NROW * Ll];
__device__ float g_q_down [NROW * Ll];
__device__ float g_k  [NROW * Cc];
__device__ float g_q  [NROW * Cc];
__device__ float g_v  [NROW * Cc];
__device__ float g_ctx[NROW * Cc];
__device__ float g_biasT[(size_t)Bb * Hh * Tt * Tt];   // [b][h][q][k], 268MB
// tf32-rounded copies of inputs/weights
__device__ float g_xt   [NROW * Cc];
__device__ float g_Wckv [Cc * Ll];
__device__ float g_Wcq  [Cc * Ll];
__device__ float g_Wkc  [Ll * Cc];
__device__ float g_Wqc  [Ll * Cc];
__device__ float g_Wvc  [Ll * Cc];
__device__ float g_Wproj[Cc * Cc];

// ---------------------------------------------------------------------------
// tf32 helpers
// ---------------------------------------------------------------------------
__device__ __forceinline__ float ftf32(float x) {
    float r;
    asm("cvt.rna.tf32.f32 %0, %1;" : "=f"(r) : "f"(x));
    return r;
}

__device__ __forceinline__ void mma_tf32(
    float& c0, float& c1, float& c2, float& c3,
    float a0, float a1, float a2, float a3,
    float b0, float b1)
{
    asm volatile(
        "mma.sync.aligned.m16n8k8.row.col.f32.tf32.tf32.f32 "
        "{%0,%1,%2,%3},{%4,%5,%6,%7},{%8,%9},{%0,%1,%2,%3};\n"
        : "+f"(c0), "+f"(c1), "+f"(c2), "+f"(c3)
        : "r"(__float_as_uint(a0)), "r"(__float_as_uint(a1)),
          "r"(__float_as_uint(a2)), "r"(__float_as_uint(a3)),
          "r"(__float_as_uint(b0)), "r"(__float_as_uint(b1)));
}

__device__ __forceinline__ void cpasync16(uint32_t saddr, const void* gptr) {
    asm volatile("cp.async.cg.shared.global [%0], [%1], 16;\n"
                 :: "r"(saddr), "l"(gptr));
}
__device__ __forceinline__ void cp_commit() {
    asm volatile("cp.async.commit_group;\n");
}
template<int NW>
__device__ __forceinline__ void cp_wait() {
    asm volatile("cp.async.wait_group %0;\n" :: "n"(NW));
}

// ---------------------------------------------------------------------------
// Elementwise tf32 rounding (RNA): out[i] = tf32(in[i]); n % 1024 == 0.
// ---------------------------------------------------------------------------
__global__ __launch_bounds__(256) void cvt_tf32(
    const float* __restrict__ in, float* __restrict__ out, int n4)
{
    int i = blockIdx.x * 256 + threadIdx.x;
    if (i < n4) {
        float4 v = ((const float4*)in)[i];
        v.x = ftf32(v.x); v.y = ftf32(v.y);
        v.z = ftf32(v.z); v.w = ftf32(v.w);
        ((float4*)out)[i] = v;
    }
}

// ---------------------------------------------------------------------------
// Tensor-core GEMM (inputs pre-rounded to tf32): C[M,N] = A@B (+bias)
// Block 128x128, 256 threads, 8 warps of 32x64. K-step 16, 2-stage cp.async.
// cvt_out != 0 -> RNA-round outputs to tf32 (for intermediates feeding GEMMs)
//   As[m][k] stride 20  -> a-frag LDS conflict-free
//   Bs[k][n] stride 136 -> b-frag LDS conflict-free
// ---------------------------------------------------------------------------
#define AST 20
#define BST 136

__global__ __launch_bounds__(256) void gemm_tc(
    const float* __restrict__ A, const float* __restrict__ B,
    float* __restrict__ C, int M, int N, int K,
    const float* __restrict__ bias, int cvt_out)
{
    __shared__ float As[2][128 * AST];
    __shared__ float Bs[2][16 * BST];

    const int tid  = threadIdx.x;
    const int warp = tid >> 5;
    const int lane = tid & 31;
    const int g    = lane >> 2;
    const int tig  = lane & 3;
    const int wm   = (warp & 3) * 32;
    const int wn   = (warp >> 2) * 64;
    const int bm   = blockIdx.y * 128;
    const int bn   = blockIdx.x * 128;

    const int arow = tid >> 1;
    const int acb  = (tid & 1) * 8;
    const int brow = tid >> 4;
    const int bnc  = (tid & 15) * 8;

    uint32_t sA0 = (uint32_t)__cvta_generic_to_shared(&As[0][arow * AST + acb]);
    uint32_t sA1 = (uint32_t)__cvta_generic_to_shared(&As[1][arow * AST + acb]);
    uint32_t sB0 = (uint32_t)__cvta_generic_to_shared(&Bs[0][brow * BST + bnc]);
    uint32_t sB1 = (uint32_t)__cvta_generic_to_shared(&Bs[1][brow * BST + bnc]);

    const float* gA = A + (size_t)(bm + arow) * K + acb;
    const float* gB = B + (size_t)brow * N + bn + bnc;

    cpasync16(sA0,      gA);
    cpasync16(sA0 + 16, gA + 4);
    cpasync16(sB0,      gB);
    cpasync16(sB0 + 16, gB + 4);
    cp_commit();

    float acc[2][8][4];
    #pragma unroll
    for (int tm = 0; tm < 2; tm++)
        #pragma unroll
        for (int tn = 0; tn < 8; tn++)
            #pragma unroll
            for (int j = 0; j < 4; j++) acc[tm][tn][j] = 0.f;

    int s = 0;
    for (int k0 = 0; k0 < K; k0 += 16) {
        if (k0 + 16 < K) {
            uint32_t dA = s ? sA0 : sA1;
            uint32_t dB = s ? sB0 : sB1;
            const float* pA = gA + k0 + 16;
            const float* pB = gB + (size_t)(k0 + 16) * N;
            cpasync16(dA,      pA);
            cpasync16(dA + 16, pA + 4);
            cpasync16(dB,      pB);
            cpasync16(dB + 16, pB + 4);
            cp_commit();
            cp_wait<1>();
        } else {
            cp_wait<0>();
        }
        __syncthreads();

        const float* Ap = As[s];
        const float* Bp = Bs[s];
        #pragma unroll
        for (int kc = 0; kc < 16; kc += 8) {
            float a[2][4];
            #pragma unroll
            for (int tm = 0; tm < 2; tm++) {
                int m = wm + tm * 16;
                a[tm][0] = Ap[(m + g)     * AST + kc + tig];
                a[tm][1] = Ap[(m + g + 8) * AST + kc + tig];
                a[tm][2] = Ap[(m + g)     * AST + kc + tig + 4];
                a[tm][3] = Ap[(m + g + 8) * AST + kc + tig + 4];
            }
            #pragma unroll
            for (int tn = 0; tn < 8; tn++) {
                float b0 = Bp[(kc + tig)     * BST + wn + tn * 8 + g];
                float b1 = Bp[(kc + tig + 4) * BST + wn + tn * 8 + g];
                mma_tf32(acc[0][tn][0], acc[0][tn][1], acc[0][tn][2], acc[0][tn][3],
                         a[0][0], a[0][1], a[0][2], a[0][3], b0, b1);
                mma_tf32(acc[1][tn][0], acc[1][tn][1], acc[1][tn][2], acc[1][tn][3],
                         a[1][0], a[1][1], a[1][2], a[1][3], b0, b1);
            }
        }
        __syncthreads();
        s ^= 1;
    }

    #pragma unroll
    for (int tn = 0; tn < 8; tn++) {
        int col = bn + wn + tn * 8 + 2 * tig;
        float2 bv = {0.f, 0.f};
        if (bias) bv = *(const float2*)&bias[col];
        #pragma unroll
        for (int tm = 0; tm < 2; tm++) {
            int r0 = bm + wm + tm * 16 + g;
            float2 w0 = {acc[tm][tn][0] + bv.x, acc[tm][tn][1] + bv.y};
            float2 w1 = {acc[tm][tn][2] + bv.x, acc[tm][tn][3] + bv.y};
            if (cvt_out) {
                w0.x = ftf32(w0.x); w0.y = ftf32(w0.y);
                w1.x = ftf32(w1.x); w1.y = ftf32(w1.y);
            }
            *(float2*)&C[(size_t)r0 * N + col]       = w0;
            *(float2*)&C[(size_t)(r0 + 8) * N + col] = w1;
        }
    }
}

// ---------------------------------------------------------------------------
// Transpose interaction matrix: in[b][k][q][h] -> out[b][h][q][k]
// ---------------------------------------------------------------------------
__global__ __launch_bounds__(256) void transpose_bias(
    const float* __restrict__ in, float* __restrict__ out)
{
    __shared__ float tile[32 * 129];
    const int k0 = blockIdx.x * 32;
    const int q0 = blockIdx.y * 8;
    const int b  = blockIdx.z;

    const size_t ibase = ((size_t)(b * Tt + k0) * Tt + q0) * Hh;
    #pragma unroll
    for (int it = 0; it < 16; it++) {
        int t  = it * 256 + threadIdx.x;
        int kk = t >> 7;
        int r  = t & 127;
        tile[kk * 129 + r] = in[ibase + (size_t)kk * (Tt * Hh) + r];
    }
    __syncthreads();
    #pragma unroll
    for (int it = 0; it < 16; it++) {
        int t  = it * 256 + threadIdx.x;
        int kk = t & 31;
        int o  = t >> 5;
        int h  = o >> 3;
        int qq = o & 7;
        out[((size_t)(b * Hh + h) * Tt + q0 + qq) * Tt + k0 + kk] =
            tile[kk * 129 + qq * 16 + h];
    }
}

// ---------------------------------------------------------------------------
// Tensor-core flash attention (tf32 mma.sync.m16n8k8).
// Block = 128 threads (4 warps); tile 64 q x 64 k.
// Writes ctx RNA-rounded to tf32 (feeds the proj GEMM's A operand).
// ---------------------------------------------------------------------------
#define QS 68
#define KS 68
#define VS 72

__global__ __launch_bounds__(128) void attn_tc(
    const float* __restrict__ Qm, const float* __restrict__ Km,
    const float* __restrict__ Vm, const float* __restrict__ biasT,
    const int* __restrict__ pad, float* __restrict__ ctx)
{
    extern __shared__ float sm[];
    float* Qs = sm;               // [64][QS]
    float* KP = Qs + 64 * QS;     // [64][KS] : K tile, reused as P
    float* Vs = KP + 64 * KS;     // [64][VS]

    const int qt = (gridDim.x - 1) - blockIdx.x;   // heavy tiles first
    const int h  = blockIdx.y;
    const int b  = blockIdx.z;
    const int tid  = threadIdx.x;
    const int warp = tid >> 5;
    const int lane = tid & 31;
    const int g    = lane >> 2;
    const int tig  = lane & 3;

    const int qrow0 = warp * 16 + g;
    const int qg0 = qt * 64 + qrow0;
    const int qg1 = qg0 + 8;

    const float* bias_bh = biasT + (size_t)(b * Hh + h) * Tt * Tt;
    const int pm0 = pad[b * Tt + qg0];
    const int pm1 = pad[b * Tt + qg1];

    // load Q tile, fold softmax scale, convert tf32
    for (int i = tid; i < 64 * 16; i += 128) {
        int row = i >> 4, c4 = (i & 15) * 4;
        float4 qv = *(const float4*)&Qm[(size_t)(b * Tt + qt * 64 + row) * Cc + h * Dd + c4];
        Qs[row * QS + c4 + 0] = ftf32(qv.x * 0.125f);
        Qs[row * QS + c4 + 1] = ftf32(qv.y * 0.125f);
        Qs[row * QS + c4 + 2] = ftf32(qv.z * 0.125f);
        Qs[row * QS + c4 + 3] = ftf32(qv.w * 0.125f);
    }

    float m0 = -INFINITY, m1 = -INFINITY, l0 = 0.f, l1 = 0.f;
    float o[8][4];
    #pragma unroll
    for (int n = 0; n < 8; n++)
        #pragma unroll
        for (int j = 0; j < 4; j++) o[n][j] = 0.f;

    for (int kt = 0; kt <= qt; kt++) {
        __syncthreads();
        for (int i = tid; i < 64 * 16; i += 128) {
            int row = i >> 4, c4 = (i & 15) * 4;
            size_t grow = (size_t)(b * Tt + kt * 64 + row) * Cc + h * Dd + c4;
            float4 kv = *(const float4*)&Km[grow];
            float4 vv = *(const float4*)&Vm[grow];
            KP[row * KS + c4 + 0] = ftf32(kv.x);
            KP[row * KS + c4 + 1] = ftf32(kv.y);
            KP[row * KS + c4 + 2] = ftf32(kv.z);
            KP[row * KS + c4 + 3] = ftf32(kv.w);
            Vs[row * VS + c4 + 0] = ftf32(vv.x);
            Vs[row * VS + c4 + 1] = ftf32(vv.y);
            Vs[row * VS + c4 + 2] = ftf32(vv.z);
            Vs[row * VS + c4 + 3] = ftf32(vv.w);
        }
        __syncthreads();

        // ---- S = Q @ K^T ----
        float s[8][4];
        #pragma unroll
        for (int n = 0; n < 8; n++)
            #pragma unroll
            for (int j = 0; j < 4; j++) s[n][j] = 0.f;

        #pragma unroll
        for (int kc = 0; kc < 64; kc += 8) {
            float a0 = Qs[(warp * 16 + g)     * QS + kc + tig];
            float a1 = Qs[(warp * 16 + g + 8) * QS + kc + tig];
            float a2 = Qs[(warp * 16 + g)     * QS + kc + tig + 4];
            float a3 = Qs[(warp * 16 + g + 8) * QS + kc + tig + 4];
            #pragma unroll
            for (int n = 0; n < 8; n++) {
                float b0 = KP[(n * 8 + g) * KS + kc + tig];
                float b1 = KP[(n * 8 + g) * KS + kc + tig + 4];
                mma_tf32(s[n][0], s[n][1], s[n][2], s[n][3], a0, a1, a2, a3, b0, b1);
            }
        }

        // ---- mask + bias ----
        const int kbase = kt * 64;
        const bool diag = (kt == qt);
        #pragma unroll
        for (int n = 0; n < 8; n++) {
            int kg = kbase + n * 8 + 2 * tig;
            float2 bi0 = *(const float2*)&bias_bh[(size_t)qg0 * Tt + kg];
            float2 bi1 = *(const float2*)&bias_bh[(size_t)qg1 * Tt + kg];
            s[n][0] = (pm0 ? s[n][0] : -1e9f) + bi0.x;
            s[n][1] = (pm0 ? s[n][1] : -1e9f) + bi0.y;
            s[n][2] = (pm1 ? s[n][2] : -1e9f) + bi1.x;
            s[n][3] = (pm1 ? s[n][3] : -1e9f) + bi1.y;
            if (diag) {
                if (kg     > qg0) s[n][0] = -INFINITY;
                if (kg + 1 > qg0) s[n][1] = -INFINITY;
                if (kg     > qg1) s[n][2] = -INFINITY;
                if (kg + 1 > qg1) s[n][3] = -INFINITY;
            }
        }

        // ---- online softmax ----
        float rm0 = -INFINITY, rm1 = -INFINITY;
        #pragma unroll
        for (int n = 0; n < 8; n++) {
            rm0 = fmaxf(rm0, fmaxf(s[n][0], s[n][1]));
            rm1 = fmaxf(rm1, fmaxf(s[n][2], s[n][3]));
        }
        rm0 = fmaxf(rm0, __shfl_xor_sync(0xffffffffu, rm0, 1));
        rm0 = fmaxf(rm0, __shfl_xor_sync(0xffffffffu, rm0, 2));
        rm1 = fmaxf(rm1, __shfl_xor_sync(0xffffffffu, rm1, 1));
        rm1 = fmaxf(rm1, __shfl_xor_sync(0xffffffffu, rm1, 2));

        float mn0 = fmaxf(m0, rm0);
        float mn1 = fmaxf(m1, rm1);
        float al0 = __expf(m0 - mn0);
        float al1 = __expf(m1 - mn1);
        m0 = mn0; m1 = mn1;

        float rs0 = 0.f, rs1 = 0.f;
        #pragma unroll
        for (int n = 0; n < 8; n++) {
            s[n][0] = __expf(s[n][0] - mn0);
            s[n][1] = __expf(s[n][1] - mn0);
            s[n][2] = __expf(s[n][2] - mn1);
            s[n][3] = __expf(s[n][3] - mn1);
            rs0 += s[n][0] + s[n][1];
            rs1 += s[n][2] + s[n][3];
        }
        rs0 += __shfl_xor_sync(0xffffffffu, rs0, 1);
        rs0 += __shfl_xor_sync(0xffffffffu, rs0, 2);
        rs1 += __shfl_xor_sync(0xffffffffu, rs1, 1);
        rs1 += __shfl_xor_sync(0xffffffffu, rs1, 2);
        l0 = l0 * al0 + rs0;
        l1 = l1 * al1 + rs1;

        #pragma unroll
        for (int n = 0; n < 8; n++) {
            o[n][0] *= al0; o[n][1] *= al0;
            o[n][2] *= al1; o[n][3] *= al1;
        }

        __syncthreads();
        #pragma unroll
        for (int n = 0; n < 8; n++) {
            KP[(warp * 16 + g)     * KS + n * 8 + 2 * tig]     = ftf32(s[n][0]);
            KP[(warp * 16 + g)     * KS + n * 8 + 2 * tig + 1] = ftf32(s[n][1]);
            KP[(warp * 16 + g + 8) * KS + n * 8 + 2 * tig]     = ftf32(s[n][2]);
            KP[(warp * 16 + g + 8) * KS + n * 8 + 2 * tig + 1] = ftf32(s[n][3]);
        }
        __syncthreads();

        // ---- O += P @ V ----
        #pragma unroll
        for (int kc = 0; kc < 64; kc += 8) {
            float a0 = KP[(warp * 16 + g)     * KS + kc + tig];
            float a1 = KP[(warp * 16 + g + 8) * KS + kc + tig];
            float a2 = KP[(warp * 16 + g)     * KS + kc + tig + 4];
            float a3 = KP[(warp * 16 + g + 8) * KS + kc + tig + 4];
            #pragma unroll
            for (int n = 0; n < 8; n++) {
                float b0 = Vs[(kc + tig)     * VS + n * 8 + g];
                float b1 = Vs[(kc + tig + 4) * VS + n * 8 + g];
                mma_tf32(o[n][0], o[n][1], o[n][2], o[n][3], a0, a1, a2, a3, b0, b1);
            }
        }
    }

    // epilogue: normalize, RNA-round to tf32 (ctx feeds proj GEMM A-side)
    float inv0 = 1.f / l0;
    float inv1 = 1.f / l1;
    #pragma unroll
    for (int n = 0; n < 8; n++) {
        int d = n * 8 + 2 * tig;
        float2 r0 = {ftf32(o[n][0] * inv0), ftf32(o[n][1] * inv0)};
        float2 r1 = {ftf32(o[n][2] * inv1), ftf32(o[n][3] * inv1)};
        *(float2*)&ctx[(size_t)(b * Tt + qg0) * Cc + h * Dd + d] = r0;
        *(float2*)&ctx[(size_t)(b * Tt + qg1) * Cc + h * Dd + d] = r1;
    }
}

// ---------------------------------------------------------------------------
extern "C" void kernel_launch(void* const* d_in, const int* in_sizes, int n_in,
                              void* d_out, int out_size)
{
    const float* x      = (const float*)d_in[0];
    const int*   pmask  = (const int*)  d_in[1];
    const float* inter  = (const float*)d_in[2];
    const float* W_ckv  = (const float*)d_in[3];
    const float* W_cq   = (const float*)d_in[4];
    const float* W_kc   = (const float*)d_in[5];
    const float* W_qc   = (const float*)d_in[6];
    const float* W_vc   = (const float*)d_in[7];
    const float* W_proj = (const float*)d_in[8];
    const float* b_proj = (const float*)d_in[9];
    float* out = (float*)d_out;

    float *kv_down, *q_down, *k, *q, *v, *ctx, *biasT;
    float *xt, *wckv, *wcq, *wkc, *wqc, *wvc, *wproj;
    cudaGetSymbolAddress((void**)&kv_down, g_kv_down);
    cudaGetSymbolAddress((void**)&q_down,  g_q_down);
    cudaGetSymbolAddress((void**)&k,       g_k);
    cudaGetSymbolAddress((void**)&q,       g_q);
    cudaGetSymbolAddress((void**)&v,       g_v);
    cudaGetSymbolAddress((void**)&ctx,     g_ctx);
    cudaGetSymbolAddress((void**)&biasT,   g_biasT);
    cudaGetSymbolAddress((void**)&xt,      g_xt);
    cudaGetSymbolAddress((void**)&wckv,    g_Wckv);
    cudaGetSymbolAddress((void**)&wcq,     g_Wcq);
    cudaGetSymbolAddress((void**)&wkc,     g_Wkc);
    cudaGetSymbolAddress((void**)&wqc,     g_Wqc);
    cudaGetSymbolAddress((void**)&wvc,     g_Wvc);
    cudaGetSymbolAddress((void**)&wproj,   g_Wproj);

    // pre-round inputs/weights to tf32 (RNA)
    auto cvt = [](const float* in, float* outp, int n) {
        int n4 = n / 4;
        cvt_tf32<<<(n4 + 255) / 256, 256>>>(in, outp, n4);
    };
    cvt(x,      xt,    NROW * Cc);
    cvt(W_ckv,  wckv,  Cc * Ll);
    cvt(W_cq,   wcq,   Cc * Ll);
    cvt(W_kc,   wkc,   Ll * Cc);
    cvt(W_qc,   wqc,   Ll * Cc);
    cvt(W_vc,   wvc,   Ll * Cc);
    cvt(W_proj, wproj, Cc * Cc);

    // transpose interaction matrix (independent of GEMM chain)
    dim3 gT(Tt / 32, Tt / 8, Bb);
    transpose_bias<<<gT, 256>>>(inter, biasT);

    // down-projections: [4096,1024] @ [1024,256] -> tf32-rounded outputs
    dim3 gDown(Ll / 128, NROW / 128);
    gemm_tc<<<gDown, 256>>>(xt, wckv, kv_down, NROW, Ll, Cc, nullptr, 1);
    gemm_tc<<<gDown, 256>>>(xt, wcq,  q_down,  NROW, Ll, Cc, nullptr, 1);

    // up-projections: [4096,256] @ [256,1024] (attention re-rounds anyway)
    dim3 gUp(Cc / 128, NROW / 128);
    gemm_tc<<<gUp, 256>>>(kv_down, wkc, k, NROW, Cc, Ll, nullptr, 0);
    gemm_tc<<<gUp, 256>>>(q_down,  wqc, q, NROW, Cc, Ll, nullptr, 0);
    gemm_tc<<<gUp, 256>>>(kv_down, wvc, v, NROW, Cc, Ll, nullptr, 0);

    // tensor-core flash attention
    size_t smem = (64 * QS + 64 * KS + 64 * VS) * sizeof(float);  // 53248 B
    cudaFuncSetAttribute(attn_tc, cudaFuncAttributeMaxDynamicSharedMemorySize,
                         (int)smem);
    dim3 gAttn(Tt / 64, Hh, Bb);
    attn_tc<<<gAttn, 128, smem>>>(q, k, v, biasT, pmask, ctx);

    // output projection with bias (final: keep full fp32)
    dim3 gProj(Cc / 128, NROW / 128);
    gemm_tc<<<gProj, 256>>>(ctx, wproj, out, NROW, Cc, Cc, b_proj, 0);
}

// round 10
// speedup vs baseline: 4.2420x; 1.0186x over previous
#include <cuda_runtime.h>
#include <cuda_bf16.h>
#include <math.h>
#include <stdint.h>

// Problem constants
#define Bb 4
#define Tt 1024
#define Cc 1024
#define Hh 16
#define Ll 256
#define Dd 64
#define NROW (Bb*Tt)   // 4096

// Scratch (allocation-free: __device__ globals)
__device__ float g_xt    [NROW * Cc];          // tf32(x)
__device__ float g_Wdown [Cc * 512];           // tf32(W_ckv) | tf32(W_cq)
__device__ float g_Wkvup [Ll * 2048];          // tf32(W_kc) | tf32(W_vc)
__device__ float g_Wqc   [Ll * Cc];            // tf32(W_qc) * 0.125
__device__ float g_Wproj [Cc * Cc];            // tf32(W_proj)
__device__ float g_down  [NROW * 512];         // kv_down | q_down  (tf32)
__device__ float g_kv    [NROW * 2048];        // k | v  (tf32)
__device__ float g_q     [NROW * Cc];          // q (tf32, pre-scaled)
__device__ float g_ctx   [NROW * Cc];
__device__ float g_biasT [(size_t)Bb * Hh * Tt * Tt];   // [b][h][q][k]

// ---------------------------------------------------------------------------
// tf32 helpers
// ---------------------------------------------------------------------------
__device__ __forceinline__ float ftf32(float x) {
    float r;
    asm("cvt.rna.tf32.f32 %0, %1;" : "=f"(r) : "f"(x));
    return r;
}

__device__ __forceinline__ void mma_tf32(
    float& c0, float& c1, float& c2, float& c3,
    float a0, float a1, float a2, float a3,
    float b0, float b1)
{
    asm volatile(
        "mma.sync.aligned.m16n8k8.row.col.f32.tf32.tf32.f32 "
        "{%0,%1,%2,%3},{%4,%5,%6,%7},{%8,%9},{%0,%1,%2,%3};\n"
        : "+f"(c0), "+f"(c1), "+f"(c2), "+f"(c3)
        : "r"(__float_as_uint(a0)), "r"(__float_as_uint(a1)),
          "r"(__float_as_uint(a2)), "r"(__float_as_uint(a3)),
          "r"(__float_as_uint(b0)), "r"(__float_as_uint(b1)));
}

__device__ __forceinline__ void cpasync16(uint32_t saddr, const void* gptr) {
    asm volatile("cp.async.cg.shared.global [%0], [%1], 16;\n"
                 :: "r"(saddr), "l"(gptr));
}
__device__ __forceinline__ void cp_commit() {
    asm volatile("cp.async.commit_group;\n");
}
template<int NW>
__device__ __forceinline__ void cp_wait() {
    asm volatile("cp.async.wait_group %0;\n" :: "n"(NW));
}

// ---------------------------------------------------------------------------
// Elementwise tf32 rounding with optional scale and output stride:
//   out[r*ldout + c] = tf32(in[r*cols + c]) * scale     (scale = 2^-k, exact)
// rows*cols % 4 == 0, cols % 4 == 0, ldout % 4 == 0.
// ---------------------------------------------------------------------------
__global__ __launch_bounds__(256) void cvt_tf32s(
    const float* __restrict__ in, float* __restrict__ out,
    int cols, int ldout, int n4, float scale)
{
    int i = blockIdx.x * 256 + threadIdx.x;
    if (i >= n4) return;
    int c4 = cols >> 2;
    int r  = i / c4;
    int c  = (i - r * c4) * 4;
    float4 v = *(const float4*)&in[(size_t)r * cols + c];
    v.x = ftf32(v.x) * scale; v.y = ftf32(v.y) * scale;
    v.z = ftf32(v.z) * scale; v.w = ftf32(v.w) * scale;
    *(float4*)&out[(size_t)r * ldout + c] = v;
}

// ---------------------------------------------------------------------------
// Tensor-core GEMM (inputs pre-rounded to tf32): C[M,N] = A@B (+bias)
// Block 128x128, 256 threads, 8 warps of 32x64. K-step 16, 2-stage cp.async.
// A row stride lda, B row stride ldb, C row stride ldc.
// cvt_out != 0 -> RNA-round outputs to tf32.
// ---------------------------------------------------------------------------
#define AST 20
#define BST 136

__global__ __launch_bounds__(256) void gemm_tc(
    const float* __restrict__ A, const float* __restrict__ B,
    float* __restrict__ C, int N, int K, int lda, int ldb, int ldc,
    const float* __restrict__ bias, int cvt_out)
{
    __shared__ float As[2][128 * AST];
    __shared__ float Bs[2][16 * BST];

    const int tid  = threadIdx.x;
    const int warp = tid >> 5;
    const int lane = tid & 31;
    const int g    = lane >> 2;
    const int tig  = lane & 3;
    const int wm   = (warp & 3) * 32;
    const int wn   = (warp >> 2) * 64;
    const int bm   = blockIdx.y * 128;
    const int bn   = blockIdx.x * 128;

    const int arow = tid >> 1;
    const int acb  = (tid & 1) * 8;
    const int brow = tid >> 4;
    const int bnc  = (tid & 15) * 8;

    uint32_t sA0 = (uint32_t)__cvta_generic_to_shared(&As[0][arow * AST + acb]);
    uint32_t sA1 = (uint32_t)__cvta_generic_to_shared(&As[1][arow * AST + acb]);
    uint32_t sB0 = (uint32_t)__cvta_generic_to_shared(&Bs[0][brow * BST + bnc]);
    uint32_t sB1 = (uint32_t)__cvta_generic_to_shared(&Bs[1][brow * BST + bnc]);

    const float* gA = A + (size_t)(bm + arow) * lda + acb;
    const float* gB = B + (size_t)brow * ldb + bn + bnc;

    cpasync16(sA0,      gA);
    cpasync16(sA0 + 16, gA + 4);
    cpasync16(sB0,      gB);
    cpasync16(sB0 + 16, gB + 4);
    cp_commit();

    float acc[2][8][4];
    #pragma unroll
    for (int tm = 0; tm < 2; tm++)
        #pragma unroll
        for (int tn = 0; tn < 8; tn++)
            #pragma unroll
            for (int j = 0; j < 4; j++) acc[tm][tn][j] = 0.f;

    int s = 0;
    for (int k0 = 0; k0 < K; k0 += 16) {
        if (k0 + 16 < K) {
            uint32_t dA = s ? sA0 : sA1;
            uint32_t dB = s ? sB0 : sB1;
            const float* pA = gA + k0 + 16;
            const float* pB = gB + (size_t)(k0 + 16) * ldb;
            cpasync16(dA,      pA);
            cpasync16(dA + 16, pA + 4);
            cpasync16(dB,      pB);
            cpasync16(dB + 16, pB + 4);
            cp_commit();
            cp_wait<1>();
        } else {
            cp_wait<0>();
        }
        __syncthreads();

        const float* Ap = As[s];
        const float* Bp = Bs[s];
        #pragma unroll
        for (int kc = 0; kc < 16; kc += 8) {
            float a[2][4];
            #pragma unroll
            for (int tm = 0; tm < 2; tm++) {
                int m = wm + tm * 16;
                a[tm][0] = Ap[(m + g)     * AST + kc + tig];
                a[tm][1] = Ap[(m + g + 8) * AST + kc + tig];
                a[tm][2] = Ap[(m + g)     * AST + kc + tig + 4];
                a[tm][3] = Ap[(m + g + 8) * AST + kc + tig + 4];
            }
            #pragma unroll
            for (int tn = 0; tn < 8; tn++) {
                float b0 = Bp[(kc + tig)     * BST + wn + tn * 8 + g];
                float b1 = Bp[(kc + tig + 4) * BST + wn + tn * 8 + g];
                mma_tf32(acc[0][tn][0], acc[0][tn][1], acc[0][tn][2], acc[0][tn][3],
                         a[0][0], a[0][1], a[0][2], a[0][3], b0, b1);
                mma_tf32(acc[1][tn][0], acc[1][tn][1], acc[1][tn][2], acc[1][tn][3],
                         a[1][0], a[1][1], a[1][2], a[1][3], b0, b1);
            }
        }
        __syncthreads();
        s ^= 1;
    }

    #pragma unroll
    for (int tn = 0; tn < 8; tn++) {
        int col = bn + wn + tn * 8 + 2 * tig;
        float2 bv = {0.f, 0.f};
        if (bias) bv = *(const float2*)&bias[col];
        #pragma unroll
        for (int tm = 0; tm < 2; tm++) {
            int r0 = bm + wm + tm * 16 + g;
            float2 w0 = {acc[tm][tn][0] + bv.x, acc[tm][tn][1] + bv.y};
            float2 w1 = {acc[tm][tn][2] + bv.x, acc[tm][tn][3] + bv.y};
            if (cvt_out) {
                w0.x = ftf32(w0.x); w0.y = ftf32(w0.y);
                w1.x = ftf32(w1.x); w1.y = ftf32(w1.y);
            }
            *(float2*)&C[(size_t)r0 * ldc + col]       = w0;
            *(float2*)&C[(size_t)(r0 + 8) * ldc + col] = w1;
        }
    }
}

// ---------------------------------------------------------------------------
// Transpose interaction matrix: in[b][k][q][h] -> out[b][h][q][k]
// Causal skip: attention reads only k-tiles (64) <= q-tile (64); unwritten
// regions stay zero (device globals are zero-init) and are masked to -inf.
// ---------------------------------------------------------------------------
__global__ __launch_bounds__(256) void transpose_bias(
    const float* __restrict__ in, float* __restrict__ out)
{
    __shared__ float tile[32 * 129];
    const int k0 = blockIdx.x * 32;
    const int q0 = blockIdx.y * 8;
    const int b  = blockIdx.z;

    if ((k0 >> 6) > (q0 >> 6)) return;   // strictly above causal diagonal

    const size_t ibase = ((size_t)(b * Tt + k0) * Tt + q0) * Hh;
    #pragma unroll
    for (int it = 0; it < 16; it++) {
        int t  = it * 256 + threadIdx.x;
        int kk = t >> 7;
        int r  = t & 127;
        tile[kk * 129 + r] = in[ibase + (size_t)kk * (Tt * Hh) + r];
    }
    __syncthreads();
    #pragma unroll
    for (int it = 0; it < 16; it++) {
        int t  = it * 256 + threadIdx.x;
        int kk = t & 31;
        int o  = t >> 5;
        int h  = o >> 3;
        int qq = o & 7;
        out[((size_t)(b * Hh + h) * Tt + q0 + qq) * Tt + k0 + kk] =
            tile[kk * 129 + qq * 16 + h];
    }
}

// ---------------------------------------------------------------------------
// Tensor-core flash attention (tf32 mma.sync.m16n8k8).
// Q/K/V are pre-rounded tf32 (GEMM epilogues); Q pre-scaled by D^-0.5.
// Tiles loaded with cp.async. Block = 128 threads (4 warps); 64q x 64k.
// ---------------------------------------------------------------------------
#define QS 68
#define KS 68
#define VS 72

__global__ __launch_bounds__(128) void attn_tc(
    const float* __restrict__ Qm, int ldq,
    const float* __restrict__ Km, const float* __restrict__ Vm, int ldkv,
    const float* __restrict__ biasT, const int* __restrict__ pad,
    float* __restrict__ ctx)
{
    extern __shared__ float sm[];
    float* Qs = sm;               // [64][QS]
    float* KP = Qs + 64 * QS;     // [64][KS] : K tile, reused as P
    float* Vs = KP + 64 * KS;     // [64][VS]

    const int qt = (gridDim.x - 1) - blockIdx.x;   // heavy tiles first
    const int h  = blockIdx.y;
    const int b  = blockIdx.z;
    const int tid  = threadIdx.x;
    const int warp = tid >> 5;
    const int lane = tid & 31;
    const int g    = lane >> 2;
    const int tig  = lane & 3;

    const int qrow0 = warp * 16 + g;
    const int qg0 = qt * 64 + qrow0;
    const int qg1 = qg0 + 8;

    const float* bias_bh = biasT + (size_t)(b * Hh + h) * Tt * Tt;
    const int pm0 = pad[b * Tt + qg0];
    const int pm1 = pad[b * Tt + qg1];

    uint32_t qsB = (uint32_t)__cvta_generic_to_shared(Qs);
    uint32_t kpB = (uint32_t)__cvta_generic_to_shared(KP);
    uint32_t vsB = (uint32_t)__cvta_generic_to_shared(Vs);

    // async-load Q tile (pre-scaled tf32); completion covered by iter-0 wait
    for (int i = tid; i < 64 * 16; i += 128) {
        int row = i >> 4, c4 = (i & 15) * 4;
        cpasync16(qsB + (row * QS + c4) * 4,
                  &Qm[(size_t)(b * Tt + qt * 64 + row) * ldq + h * Dd + c4]);
    }
    cp_commit();

    float m0 = -INFINITY, m1 = -INFINITY, l0 = 0.f, l1 = 0.f;
    float o[8][4];
    #pragma unroll
    for (int n = 0; n < 8; n++)
        #pragma unroll
        for (int j = 0; j < 4; j++) o[n][j] = 0.f;

    for (int kt = 0; kt <= qt; kt++) {
        __syncthreads();   // prev iter done reading KP/Vs
        for (int i = tid; i < 64 * 16; i += 128) {
            int row = i >> 4, c4 = (i & 15) * 4;
            size_t gofs = (size_t)(b * Tt + kt * 64 + row) * ldkv + h * Dd + c4;
            cpasync16(kpB + (row * KS + c4) * 4, Km + gofs);
            cpasync16(vsB + (row * VS + c4) * 4, Vm + gofs);
        }
        cp_commit();
        cp_wait<0>();
        __syncthreads();

        // ---- S = Q @ K^T ----
        float s[8][4];
        #pragma unroll
        for (int n = 0; n < 8; n++)
            #pragma unroll
            for (int j = 0; j < 4; j++) s[n][j] = 0.f;

        #pragma unroll
        for (int kc = 0; kc < 64; kc += 8) {
            float a0 = Qs[(warp * 16 + g)     * QS + kc + tig];
            float a1 = Qs[(warp * 16 + g + 8) * QS + kc + tig];
            float a2 = Qs[(warp * 16 + g)     * QS + kc + tig + 4];
            float a3 = Qs[(warp * 16 + g + 8) * QS + kc + tig + 4];
            #pragma unroll
            for (int n = 0; n < 8; n++) {
                float b0 = KP[(n * 8 + g) * KS + kc + tig];
                float b1 = KP[(n * 8 + g) * KS + kc + tig + 4];
                mma_tf32(s[n][0], s[n][1], s[n][2], s[n][3], a0, a1, a2, a3, b0, b1);
            }
        }

        // ---- mask + bias ----
        const int kbase = kt * 64;
        const bool diag = (kt == qt);
        #pragma unroll
        for (int n = 0; n < 8; n++) {
            int kg = kbase + n * 8 + 2 * tig;
            float2 bi0 = *(const float2*)&bias_bh[(size_t)qg0 * Tt + kg];
            float2 bi1 = *(const float2*)&bias_bh[(size_t)qg1 * Tt + kg];
            s[n][0] = (pm0 ? s[n][0] : -1e9f) + bi0.x;
            s[n][1] = (pm0 ? s[n][1] : -1e9f) + bi0.y;
            s[n][2] = (pm1 ? s[n][2] : -1e9f) + bi1.x;
            s[n][3] = (pm1 ? s[n][3] : -1e9f) + bi1.y;
            if (diag) {
                if (kg     > qg0) s[n][0] = -INFINITY;
                if (kg + 1 > qg0) s[n][1] = -INFINITY;
                if (kg     > qg1) s[n][2] = -INFINITY;
                if (kg + 1 > qg1) s[n][3] = -INFINITY;
            }
        }

        // ---- online softmax ----
        float rm0 = -INFINITY, rm1 = -INFINITY;
        #pragma unroll
        for (int n = 0; n < 8; n++) {
            rm0 = fmaxf(rm0, fmaxf(s[n][0], s[n][1]));
            rm1 = fmaxf(rm1, fmaxf(s[n][2], s[n][3]));
        }
        rm0 = fmaxf(rm0, __shfl_xor_sync(0xffffffffu, rm0, 1));
        rm0 = fmaxf(rm0, __shfl_xor_sync(0xffffffffu, rm0, 2));
        rm1 = fmaxf(rm1, __shfl_xor_sync(0xffffffffu, rm1, 1));
        rm1 = fmaxf(rm1, __shfl_xor_sync(0xffffffffu, rm1, 2));

        float mn0 = fmaxf(m0, rm0);
        float mn1 = fmaxf(m1, rm1);
        float al0 = __expf(m0 - mn0);
        float al1 = __expf(m1 - mn1);
        m0 = mn0; m1 = mn1;

        float rs0 = 0.f, rs1 = 0.f;
        #pragma unroll
        for (int n = 0; n < 8; n++) {
            s[n][0] = __expf(s[n][0] - mn0);
            s[n][1] = __expf(s[n][1] - mn0);
            s[n][2] = __expf(s[n][2] - mn1);
            s[n][3] = __expf(s[n][3] - mn1);
            rs0 += s[n][0] + s[n][1];
            rs1 += s[n][2] + s[n][3];
        }
        rs0 += __shfl_xor_sync(0xffffffffu, rs0, 1);
        rs0 += __shfl_xor_sync(0xffffffffu, rs0, 2);
        rs1 += __shfl_xor_sync(0xffffffffu, rs1, 1);
        rs1 += __shfl_xor_sync(0xffffffffu, rs1, 2);
        l0 = l0 * al0 + rs0;
        l1 = l1 * al1 + rs1;

        #pragma unroll
        for (int n = 0; n < 8; n++) {
            o[n][0] *= al0; o[n][1] *= al0;
            o[n][2] *= al1; o[n][3] *= al1;
        }

        __syncthreads();   // all warps done reading K from KP
        #pragma unroll
        for (int n = 0; n < 8; n++) {
            KP[(warp * 16 + g)     * KS + n * 8 + 2 * tig]     = ftf32(s[n][0]);
            KP[(warp * 16 + g)     * KS + n * 8 + 2 * tig + 1] = ftf32(s[n][1]);
            KP[(warp * 16 + g + 8) * KS + n * 8 + 2 * tig]     = ftf32(s[n][2]);
            KP[(warp * 16 + g + 8) * KS + n * 8 + 2 * tig + 1] = ftf32(s[n][3]);
        }
        __syncthreads();

        // ---- O += P @ V ----
        #pragma unroll
        for (int kc = 0; kc < 64; kc += 8) {
            float a0 = KP[(warp * 16 + g)     * KS + kc + tig];
            float a1 = KP[(warp * 16 + g + 8) * KS + kc + tig];
            float a2 = KP[(warp * 16 + g)     * KS + kc + tig + 4];
            float a3 = KP[(warp * 16 + g + 8) * KS + kc + tig + 4];
            #pragma unroll
            for (int n = 0; n < 8; n++) {
                float b0 = Vs[(kc + tig)     * VS + n * 8 + g];
                float b1 = Vs[(kc + tig + 4) * VS + n * 8 + g];
                mma_tf32(o[n][0], o[n][1], o[n][2], o[n][3], a0, a1, a2, a3, b0, b1);
            }
        }
    }

    // epilogue: normalize, RNA-round to tf32 (ctx feeds proj GEMM A-side)
    float inv0 = 1.f / l0;
    float inv1 = 1.f / l1;
    #pragma unroll
    for (int n = 0; n < 8; n++) {
        int d = n * 8 + 2 * tig;
        float2 r0 = {ftf32(o[n][0] * inv0), ftf32(o[n][1] * inv0)};
        float2 r1 = {ftf32(o[n][2] * inv1), ftf32(o[n][3] * inv1)};
        *(float2*)&ctx[(size_t)(b * Tt + qg0) * Cc + h * Dd + d] = r0;
        *(float2*)&ctx[(size_t)(b * Tt + qg1) * Cc + h * Dd + d] = r1;
    }
}

// ---------------------------------------------------------------------------
extern "C" void kernel_launch(void* const* d_in, const int* in_sizes, int n_in,
                              void* d_out, int out_size)
{
    const float* x      = (const float*)d_in[0];
    const int*   pmask  = (const int*)  d_in[1];
    const float* inter  = (const float*)d_in[2];
    const float* W_ckv  = (const float*)d_in[3];
    const float* W_cq   = (const float*)d_in[4];
    const float* W_kc   = (const float*)d_in[5];
    const float* W_qc   = (const float*)d_in[6];
    const float* W_vc   = (const float*)d_in[7];
    const float* W_proj = (const float*)d_in[8];
    const float* b_proj = (const float*)d_in[9];
    float* out = (float*)d_out;

    float *xt, *wdown, *wkvup, *wqc, *wproj;
    float *down, *kv, *q, *ctx, *biasT;
    cudaGetSymbolAddress((void**)&xt,    g_xt);
    cudaGetSymbolAddress((void**)&wdown, g_Wdown);
    cudaGetSymbolAddress((void**)&wkvup, g_Wkvup);
    cudaGetSymbolAddress((void**)&wqc,   g_Wqc);
    cudaGetSymbolAddress((void**)&wproj, g_Wproj);
    cudaGetSymbolAddress((void**)&down,  g_down);
    cudaGetSymbolAddress((void**)&kv,    g_kv);
    cudaGetSymbolAddress((void**)&q,     g_q);
    cudaGetSymbolAddress((void**)&ctx,   g_ctx);
    cudaGetSymbolAddress((void**)&biasT, g_biasT);

    // pre-round inputs/weights to tf32 (RNA), with concat/scale folds
    auto cvt = [](const float* in, float* outp, int cols, int ldout, int n,
                  float scale) {
        int n4 = n / 4;
        cvt_tf32s<<<(n4 + 255) / 256, 256>>>(in, outp, cols, ldout, n4, scale);
    };
    cvt(x,      xt,           Cc,  Cc,   NROW * Cc, 1.f);
    cvt(W_ckv,  wdown,        Ll,  512,  Cc * Ll,   1.f);
    cvt(W_cq,   wdown + 256,  Ll,  512,  Cc * Ll,   1.f);
    cvt(W_kc,   wkvup,        Cc,  2048, Ll * Cc,   1.f);
    cvt(W_vc,   wkvup + 1024, Cc,  2048, Ll * Cc,   1.f);
    cvt(W_qc,   wqc,          Cc,  Cc,   Ll * Cc,   0.125f);  // fold D^-0.5
    cvt(W_proj, wproj,        Cc,  Cc,   Cc * Cc,   1.f);

    // transpose interaction matrix (causal tiles only)
    dim3 gT(Tt / 32, Tt / 8, Bb);
    transpose_bias<<<gT, 256>>>(inter, biasT);

    // merged down-projection: [4096,1024] @ [1024,512] -> kv_down|q_down
    dim3 gDown(512 / 128, NROW / 128);
    gemm_tc<<<gDown, 256>>>(xt, wdown, down, 512, Cc, Cc, 512, 512, nullptr, 1);

    // merged kv up-projection: [4096,256] @ [256,2048] -> k|v
    dim3 gKV(2048 / 128, NROW / 128);
    gemm_tc<<<gKV, 256>>>(down, wkvup, kv, 2048, Ll, 512, 2048, 2048, nullptr, 1);

    // q up-projection: [4096,256] @ [256,1024] (weights pre-scaled)
    dim3 gQ(Cc / 128, NROW / 128);
    gemm_tc<<<gQ, 256>>>(down + 256, wqc, q, Cc, Ll, 512, Cc, Cc, nullptr, 1);

    // tensor-core flash attention
    size_t smem = (64 * QS + 64 * KS + 64 * VS) * sizeof(float);  // 53248 B
    cudaFuncSetAttribute(attn_tc, cudaFuncAttributeMaxDynamicSharedMemorySize,
                         (int)smem);
    dim3 gAttn(Tt / 64, Hh, Bb);
    attn_tc<<<gAttn, 128, smem>>>(q, Cc, kv, kv + 1024, 2048, biasT, pmask, ctx);

    // output projection with bias (final: full fp32)
    dim3 gProj(Cc / 128, NROW / 128);
    gemm_tc<<<gProj, 256>>>(ctx, wproj, out, Cc, Cc, Cc, Cc, Cc, b_proj, 0);
}

// round 13
// speedup vs baseline: 4.8997x; 1.1550x over previous
#include <cuda_runtime.h>
#include <cuda_bf16.h>
#include <math.h>
#include <stdint.h>

// Problem constants
#define Bb 4
#define Tt 1024
#define Cc 1024
#define Hh 16
#define Ll 256
#define Dd 64
#define NROW (Bb*Tt)   // 4096

// Scratch (allocation-free: __device__ globals)
__device__ float g_xt    [NROW * Cc];          // tf32(x)
__device__ float g_Wdown [Cc * 512];           // tf32(W_ckv) | tf32(W_cq)
__device__ float g_Wkvup [Ll * 2048];          // tf32(W_kc) | tf32(W_vc)
__device__ float g_Wqc   [Ll * Cc];            // tf32(W_qc) * 0.125
__device__ float g_Wproj [Cc * Cc];            // tf32(W_proj)
__device__ float g_down  [NROW * 512];         // kv_down | q_down  (tf32)
__device__ float g_kv    [NROW * 2048];        // k | v  (tf32)
__device__ float g_q     [NROW * Cc];          // q (tf32, pre-scaled)
__device__ float g_ctx   [NROW * Cc];
__device__ float g_biasT [(size_t)Bb * Hh * Tt * Tt];   // [b][h][q][k]

// ---------------------------------------------------------------------------
// tf32 helpers
// ---------------------------------------------------------------------------
__device__ __forceinline__ float ftf32(float x) {
    float r;
    asm("cvt.rna.tf32.f32 %0, %1;" : "=f"(r) : "f"(x));
    return r;
}

__device__ __forceinline__ void mma_tf32(
    float& c0, float& c1, float& c2, float& c3,
    float a0, float a1, float a2, float a3,
    float b0, float b1)
{
    asm volatile(
        "mma.sync.aligned.m16n8k8.row.col.f32.tf32.tf32.f32 "
        "{%0,%1,%2,%3},{%4,%5,%6,%7},{%8,%9},{%0,%1,%2,%3};\n"
        : "+f"(c0), "+f"(c1), "+f"(c2), "+f"(c3)
        : "r"(__float_as_uint(a0)), "r"(__float_as_uint(a1)),
          "r"(__float_as_uint(a2)), "r"(__float_as_uint(a3)),
          "r"(__float_as_uint(b0)), "r"(__float_as_uint(b1)));
}

__device__ __forceinline__ void cpasync16(uint32_t saddr, const void* gptr) {
    asm volatile("cp.async.cg.shared.global [%0], [%1], 16;\n"
                 :: "r"(saddr), "l"(gptr));
}
__device__ __forceinline__ void cp_commit() {
    asm volatile("cp.async.commit_group;\n");
}
template<int NW>
__device__ __forceinline__ void cp_wait() {
    asm volatile("cp.async.wait_group %0;\n" :: "n"(NW));
}

// ---------------------------------------------------------------------------
// Elementwise tf32 rounding with optional scale and output stride.
// ---------------------------------------------------------------------------
__global__ __launch_bounds__(256) void cvt_tf32s(
    const float* __restrict__ in, float* __restrict__ out,
    int cols, int ldout, int n4, float scale)
{
    int i = blockIdx.x * 256 + threadIdx.x;
    if (i >= n4) return;
    int c4 = cols >> 2;
    int r  = i / c4;
    int c  = (i - r * c4) * 4;
    float4 v = *(const float4*)&in[(size_t)r * cols + c];
    v.x = ftf32(v.x) * scale; v.y = ftf32(v.y) * scale;
    v.z = ftf32(v.z) * scale; v.w = ftf32(v.w) * scale;
    *(float4*)&out[(size_t)r * ldout + c] = v;
}

// ---------------------------------------------------------------------------
// Tensor-core GEMM (inputs pre-rounded tf32): C[M,N] = A@B (+bias)
// Block 128x128, 256 threads, 8 warps of 32x64. K-step 32, 2-stage cp.async,
// dynamic smem. cvt_out != 0 -> RNA-round outputs to tf32.
// ---------------------------------------------------------------------------
#define AST 36
#define BST 136
#define GEMM_SMEM ((2*128*AST + 2*32*BST) * 4)   // 71680 B

__global__ __launch_bounds__(256, 2) void gemm_tc(
    const float* __restrict__ A, const float* __restrict__ B,
    float* __restrict__ C, int N, int K, int lda, int ldb, int ldc,
    const float* __restrict__ bias, int cvt_out)
{
    extern __shared__ float gsm[];
    float* Asm = gsm;                       // 2 stages of [128][AST]
    float* Bsm = gsm + 2 * 128 * AST;       // 2 stages of [32][BST]

    const int tid  = threadIdx.x;
    const int warp = tid >> 5;
    const int lane = tid & 31;
    const int g    = lane >> 2;
    const int tig  = lane & 3;
    const int wm   = (warp & 3) * 32;
    const int wn   = (warp >> 2) * 64;
    const int bm   = blockIdx.y * 128;
    const int bn   = blockIdx.x * 128;

    const int arow = tid >> 1;            // 0..127
    const int acb  = (tid & 1) * 8;       // 0 or 8 (also +16)
    const int brow = tid >> 4;            // 0..15  (also +16)
    const int bnc  = (tid & 15) * 8;

    uint32_t sA[2], sB[2];
    sA[0] = (uint32_t)__cvta_generic_to_shared(&Asm[arow * AST + acb]);
    sA[1] = sA[0] + 128 * AST * 4;
    sB[0] = (uint32_t)__cvta_generic_to_shared(&Bsm[brow * BST + bnc]);
    sB[1] = sB[0] + 32 * BST * 4;

    const float* gA = A + (size_t)(bm + arow) * lda + acb;
    const float* gB = B + (size_t)brow * ldb + bn + bnc;

    // prologue: stage 0 (cols acb..+8, acb+16..+24; rows brow, brow+16)
    cpasync16(sA[0],           gA);
    cpasync16(sA[0] + 16,      gA + 4);
    cpasync16(sA[0] + 64,      gA + 16);
    cpasync16(sA[0] + 80,      gA + 20);
    cpasync16(sB[0],           gB);
    cpasync16(sB[0] + 16,      gB + 4);
    cpasync16(sB[0] + 16*BST*4,      gB + (size_t)16 * ldb);
    cpasync16(sB[0] + 16*BST*4 + 16, gB + (size_t)16 * ldb + 4);
    cp_commit();

    float acc[2][8][4];
    #pragma unroll
    for (int tm = 0; tm < 2; tm++)
        #pragma unroll
        for (int tn = 0; tn < 8; tn++)
            #pragma unroll
            for (int j = 0; j < 4; j++) acc[tm][tn][j] = 0.f;

    int s = 0;
    for (int k0 = 0; k0 < K; k0 += 32) {
        if (k0 + 32 < K) {
            uint32_t dA = sA[s ^ 1], dB = sB[s ^ 1];
            const float* pA = gA + k0 + 32;
            const float* pB = gB + (size_t)(k0 + 32) * ldb;
            cpasync16(dA,      pA);
            cpasync16(dA + 16, pA + 4);
            cpasync16(dA + 64, pA + 16);
            cpasync16(dA + 80, pA + 20);
            cpasync16(dB,      pB);
            cpasync16(dB + 16, pB + 4);
            cpasync16(dB + 16*BST*4,      pB + (size_t)16 * ldb);
            cpasync16(dB + 16*BST*4 + 16, pB + (size_t)16 * ldb + 4);
            cp_commit();
            cp_wait<1>();
        } else {
            cp_wait<0>();
        }
        __syncthreads();

        const float* Ap = Asm + s * 128 * AST;
        const float* Bp = Bsm + s * 32 * BST;
        #pragma unroll
        for (int kc = 0; kc < 32; kc += 8) {
            float a[2][4];
            #pragma unroll
            for (int tm = 0; tm < 2; tm++) {
                int m = wm + tm * 16;
                a[tm][0] = Ap[(m + g)     * AST + kc + tig];
                a[tm][1] = Ap[(m + g + 8) * AST + kc + tig];
                a[tm][2] = Ap[(m + g)     * AST + kc + tig + 4];
                a[tm][3] = Ap[(m + g + 8) * AST + kc + tig + 4];
            }
            #pragma unroll
            for (int tn = 0; tn < 8; tn++) {
                float b0 = Bp[(kc + tig)     * BST + wn + tn * 8 + g];
                float b1 = Bp[(kc + tig + 4) * BST + wn + tn * 8 + g];
                mma_tf32(acc[0][tn][0], acc[0][tn][1], acc[0][tn][2], acc[0][tn][3],
                         a[0][0], a[0][1], a[0][2], a[0][3], b0, b1);
                mma_tf32(acc[1][tn][0], acc[1][tn][1], acc[1][tn][2], acc[1][tn][3],
                         a[1][0], a[1][1], a[1][2], a[1][3], b0, b1);
            }
        }
        __syncthreads();
        s ^= 1;
    }

    #pragma unroll
    for (int tn = 0; tn < 8; tn++) {
        int col = bn + wn + tn * 8 + 2 * tig;
        float2 bv = {0.f, 0.f};
        if (bias) bv = *(const float2*)&bias[col];
        #pragma unroll
        for (int tm = 0; tm < 2; tm++) {
            int r0 = bm + wm + tm * 16 + g;
            float2 w0 = {acc[tm][tn][0] + bv.x, acc[tm][tn][1] + bv.y};
            float2 w1 = {acc[tm][tn][2] + bv.x, acc[tm][tn][3] + bv.y};
            if (cvt_out) {
                w0.x = ftf32(w0.x); w0.y = ftf32(w0.y);
                w1.x = ftf32(w1.x); w1.y = ftf32(w1.y);
            }
            *(float2*)&C[(size_t)r0 * ldc + col]       = w0;
            *(float2*)&C[(size_t)(r0 + 8) * ldc + col] = w1;
        }
    }
}

// ---------------------------------------------------------------------------
// Transpose interaction matrix: in[b][k][q][h] -> out[b][h][q][k]
// Causal skip: tiles strictly above the 64-diagonal never read -> stay zero.
// ---------------------------------------------------------------------------
__global__ __launch_bounds__(256) void transpose_bias(
    const float* __restrict__ in, float* __restrict__ out)
{
    __shared__ float tile[32 * 129];
    const int k0 = blockIdx.x * 32;
    const int q0 = blockIdx.y * 8;
    const int b  = blockIdx.z;

    if ((k0 >> 6) > (q0 >> 6)) return;

    const size_t ibase = ((size_t)(b * Tt + k0) * Tt + q0) * Hh;
    #pragma unroll
    for (int it = 0; it < 16; it++) {
        int t  = it * 256 + threadIdx.x;
        int kk = t >> 7;
        int r  = t & 127;
        tile[kk * 129 + r] = in[ibase + (size_t)kk * (Tt * Hh) + r];
    }
    __syncthreads();
    #pragma unroll
    for (int it = 0; it < 16; it++) {
        int t  = it * 256 + threadIdx.x;
        int kk = t & 31;
        int o  = t >> 5;
        int h  = o >> 3;
        int qq = o & 7;
        out[((size_t)(b * Hh + h) * Tt + q0 + qq) * Tt + k0 + kk] =
            tile[kk * 129 + qq * 16 + h];
    }
}

// ---------------------------------------------------------------------------
// Tensor-core flash attention (tf32 mma.sync.m16n8k8).
// 256 threads / 8 warps; tile 128q x 64k; warp w owns q rows [16w,16w+16).
// Dedicated P buffer -> P relayout is warp-private (syncwarp only);
// 2 block syncs per k-tile. Q/K/V pre-rounded tf32, Q pre-scaled.
// ---------------------------------------------------------------------------
#define BQ 128
#define QS 68
#define PS 68
#define KS 68
#define VS 72
#define ATTN_SMEM ((BQ*QS + BQ*PS + 64*KS + 64*VS) * 4)   // 105472 B

__global__ __launch_bounds__(256, 2) void attn_tc(
    const float* __restrict__ Qm, int ldq,
    const float* __restrict__ Km, const float* __restrict__ Vm, int ldkv,
    const float* __restrict__ biasT, const int* __restrict__ pad,
    float* __restrict__ ctx)
{
    extern __shared__ float sm[];
    float* Qs = sm;                    // [128][QS]
    float* Ps = Qs + BQ * QS;          // [128][PS]
    float* Ks = Ps + BQ * PS;          // [64][KS]
    float* Vs = Ks + 64 * KS;          // [64][VS]

    const int qt = (gridDim.x - 1) - blockIdx.x;   // heavy tiles first
    const int h  = blockIdx.y;
    const int b  = blockIdx.z;
    const int tid  = threadIdx.x;
    const int warp = tid >> 5;
    const int lane = tid & 31;
    const int g    = lane >> 2;
    const int tig  = lane & 3;

    const int r0  = warp * 16 + g;          // local q row (c0/c1)
    const int qg0 = qt * BQ + r0;
    const int qg1 = qg0 + 8;

    const float* bias_bh = biasT + (size_t)(b * Hh + h) * Tt * Tt;
    const int pm0 = pad[b * Tt + qg0];
    const int pm1 = pad[b * Tt + qg1];

    uint32_t qsB = (uint32_t)__cvta_generic_to_shared(Qs);
    uint32_t ksB = (uint32_t)__cvta_generic_to_shared(Ks);
    uint32_t vsB = (uint32_t)__cvta_generic_to_shared(Vs);

    // async-load Q tile (128x64); completion covered by iter-0 wait
    for (int i = tid; i < BQ * 16; i += 256) {
        int row = i >> 4, c4 = (i & 15) * 4;
        cpasync16(qsB + (row * QS + c4) * 4,
                  &Qm[(size_t)(b * Tt + qt * BQ + row) * ldq + h * Dd + c4]);
    }
    cp_commit();

    float m0 = -INFINITY, m1 = -INFINITY, l0 = 0.f, l1 = 0.f;
    float o[8][4];
    #pragma unroll
    for (int n = 0; n < 8; n++)
        #pragma unroll
        for (int j = 0; j < 4; j++) o[n][j] = 0.f;

    const int ktmax = 2 * qt + 1;
    for (int kt = 0; kt <= ktmax; kt++) {
        __syncthreads();   // prev iter done reading Ks/Vs
        for (int i = tid; i < 64 * 16; i += 256) {
            int row = i >> 4, c4 = (i & 15) * 4;
            size_t gofs = (size_t)(b * Tt + kt * 64 + row) * ldkv + h * Dd + c4;
            cpasync16(ksB + (row * KS + c4) * 4, Km + gofs);
            cpasync16(vsB + (row * VS + c4) * 4, Vm + gofs);
        }
        cp_commit();
        cp_wait<0>();
        __syncthreads();   // K/V (and Q on iter 0) ready

        // ---- S = Q @ K^T ----
        float s[8][4];
        #pragma unroll
        for (int n = 0; n < 8; n++)
            #pragma unroll
            for (int j = 0; j < 4; j++) s[n][j] = 0.f;

        #pragma unroll
        for (int kc = 0; kc < 64; kc += 8) {
            float a0 = Qs[(r0)     * QS + kc + tig];
            float a1 = Qs[(r0 + 8) * QS + kc + tig];
            float a2 = Qs[(r0)     * QS + kc + tig + 4];
            float a3 = Qs[(r0 + 8) * QS + kc + tig + 4];
            #pragma unroll
            for (int n = 0; n < 8; n++) {
                float b0 = Ks[(n * 8 + g) * KS + kc + tig];
                float b1 = Ks[(n * 8 + g) * KS + kc + tig + 4];
                mma_tf32(s[n][0], s[n][1], s[n][2], s[n][3], a0, a1, a2, a3, b0, b1);
            }
        }

        // ---- mask + bias ----
        const int kbase = kt * 64;
        const bool need0 = (kbase + 63) > qg0;
        const bool need1 = (kbase + 63) > qg1;
        #pragma unroll
        for (int n = 0; n < 8; n++) {
            int kg = kbase + n * 8 + 2 * tig;
            float2 bi0 = *(const float2*)&bias_bh[(size_t)qg0 * Tt + kg];
            float2 bi1 = *(const float2*)&bias_bh[(size_t)qg1 * Tt + kg];
            s[n][0] = (pm0 ? s[n][0] : -1e9f) + bi0.x;
            s[n][1] = (pm0 ? s[n][1] : -1e9f) + bi0.y;
            s[n][2] = (pm1 ? s[n][2] : -1e9f) + bi1.x;
            s[n][3] = (pm1 ? s[n][3] : -1e9f) + bi1.y;
            if (need0) {
                if (kg     > qg0) s[n][0] = -INFINITY;
                if (kg + 1 > qg0) s[n][1] = -INFINITY;
            }
            if (need1) {
                if (kg     > qg1) s[n][2] = -INFINITY;
                if (kg + 1 > qg1) s[n][3] = -INFINITY;
            }
        }

        // ---- online softmax (quad reduce over lanes xor 1,2) ----
        float rm0 = -INFINITY, rm1 = -INFINITY;
        #pragma unroll
        for (int n = 0; n < 8; n++) {
            rm0 = fmaxf(rm0, fmaxf(s[n][0], s[n][1]));
            rm1 = fmaxf(rm1, fmaxf(s[n][2], s[n][3]));
        }
        rm0 = fmaxf(rm0, __shfl_xor_sync(0xffffffffu, rm0, 1));
        rm0 = fmaxf(rm0, __shfl_xor_sync(0xffffffffu, rm0, 2));
        rm1 = fmaxf(rm1, __shfl_xor_sync(0xffffffffu, rm1, 1));
        rm1 = fmaxf(rm1, __shfl_xor_sync(0xffffffffu, rm1, 2));

        float mn0 = fmaxf(m0, rm0);
        float mn1 = fmaxf(m1, rm1);
        float al0 = __expf(m0 - mn0);
        float al1 = __expf(m1 - mn1);
        m0 = mn0; m1 = mn1;

        float rs0 = 0.f, rs1 = 0.f;
        #pragma unroll
        for (int n = 0; n < 8; n++) {
            s[n][0] = __expf(s[n][0] - mn0);
            s[n][1] = __expf(s[n][1] - mn0);
            s[n][2] = __expf(s[n][2] - mn1);
            s[n][3] = __expf(s[n][3] - mn1);
            rs0 += s[n][0] + s[n][1];
            rs1 += s[n][2] + s[n][3];
        }
        rs0 += __shfl_xor_sync(0xffffffffu, rs0, 1);
        rs0 += __shfl_xor_sync(0xffffffffu, rs0, 2);
        rs1 += __shfl_xor_sync(0xffffffffu, rs1, 1);
        rs1 += __shfl_xor_sync(0xffffffffu, rs1, 2);
        l0 = l0 * al0 + rs0;
        l1 = l1 * al1 + rs1;

        #pragma unroll
        for (int n = 0; n < 8; n++) {
            o[n][0] *= al0; o[n][1] *= al0;
            o[n][2] *= al1; o[n][3] *= al1;
        }

        // ---- P relayout: warp-private buffer, no block sync ----
        #pragma unroll
        for (int n = 0; n < 8; n++) {
            Ps[(r0)     * PS + n * 8 + 2 * tig]     = ftf32(s[n][0]);
            Ps[(r0)     * PS + n * 8 + 2 * tig + 1] = ftf32(s[n][1]);
            Ps[(r0 + 8) * PS + n * 8 + 2 * tig]     = ftf32(s[n][2]);
            Ps[(r0 + 8) * PS + n * 8 + 2 * tig + 1] = ftf32(s[n][3]);
        }
        __syncwarp();

        // ---- O += P @ V ----
        #pragma unroll
        for (int kc = 0; kc < 64; kc += 8) {
            float a0 = Ps[(r0)     * PS + kc + tig];
            float a1 = Ps[(r0 + 8) * PS + kc + tig];
            float a2 = Ps[(r0)     * PS + kc + tig + 4];
            float a3 = Ps[(r0 + 8) * PS + kc + tig + 4];
            #pragma unroll
            for (int n = 0; n < 8; n++) {
                float b0 = Vs[(kc + tig)     * VS + n * 8 + g];
                float b1 = Vs[(kc + tig + 4) * VS + n * 8 + g];
                mma_tf32(o[n][0], o[n][1], o[n][2], o[n][3], a0, a1, a2, a3, b0, b1);
            }
        }
    }

    // epilogue: normalize, RNA-round to tf32 (ctx feeds proj GEMM A-side)
    float inv0 = 1.f / l0;
    float inv1 = 1.f / l1;
    #pragma unroll
    for (int n = 0; n < 8; n++) {
        int d = n * 8 + 2 * tig;
        float2 w0 = {ftf32(o[n][0] * inv0), ftf32(o[n][1] * inv0)};
        float2 w1 = {ftf32(o[n][2] * inv1), ftf32(o[n][3] * inv1)};
        *(float2*)&ctx[(size_t)(b * Tt + qg0) * Cc + h * Dd + d] = w0;
        *(float2*)&ctx[(size_t)(b * Tt + qg1) * Cc + h * Dd + d] = w1;
    }
}

// ---------------------------------------------------------------------------
extern "C" void kernel_launch(void* const* d_in, const int* in_sizes, int n_in,
                              void* d_out, int out_size)
{
    const float* x      = (const float*)d_in[0];
    const int*   pmask  = (const int*)  d_in[1];
    const float* inter  = (const float*)d_in[2];
    const float* W_ckv  = (const float*)d_in[3];
    const float* W_cq   = (const float*)d_in[4];
    const float* W_kc   = (const float*)d_in[5];
    const float* W_qc   = (const float*)d_in[6];
    const float* W_vc   = (const float*)d_in[7];
    const float* W_proj = (const float*)d_in[8];
    const float* b_proj = (const float*)d_in[9];
    float* out = (float*)d_out;

    float *xt, *wdown, *wkvup, *wqc, *wproj;
    float *down, *kv, *q, *ctx, *biasT;
    cudaGetSymbolAddress((void**)&xt,    g_xt);
    cudaGetSymbolAddress((void**)&wdown, g_Wdown);
    cudaGetSymbolAddress((void**)&wkvup, g_Wkvup);
    cudaGetSymbolAddress((void**)&wqc,   g_Wqc);
    cudaGetSymbolAddress((void**)&wproj, g_Wproj);
    cudaGetSymbolAddress((void**)&down,  g_down);
    cudaGetSymbolAddress((void**)&kv,    g_kv);
    cudaGetSymbolAddress((void**)&q,     g_q);
    cudaGetSymbolAddress((void**)&ctx,   g_ctx);
    cudaGetSymbolAddress((void**)&biasT, g_biasT);

    cudaFuncSetAttribute(gemm_tc, cudaFuncAttributeMaxDynamicSharedMemorySize,
                         GEMM_SMEM);
    cudaFuncSetAttribute(attn_tc, cudaFuncAttributeMaxDynamicSharedMemorySize,
                         ATTN_SMEM);

    // pre-round inputs/weights to tf32 (RNA), with concat/scale folds
    auto cvt = [](const float* in, float* outp, int cols, int ldout, int n,
                  float scale) {
        int n4 = n / 4;
        cvt_tf32s<<<(n4 + 255) / 256, 256>>>(in, outp, cols, ldout, n4, scale);
    };
    cvt(x,      xt,           Cc,  Cc,   NROW * Cc, 1.f);
    cvt(W_ckv,  wdown,        Ll,  512,  Cc * Ll,   1.f);
    cvt(W_cq,   wdown + 256,  Ll,  512,  Cc * Ll,   1.f);
    cvt(W_kc,   wkvup,        Cc,  2048, Ll * Cc,   1.f);
    cvt(W_vc,   wkvup + 1024, Cc,  2048, Ll * Cc,   1.f);
    cvt(W_qc,   wqc,          Cc,  Cc,   Ll * Cc,   0.125f);  // fold D^-0.5
    cvt(W_proj, wproj,        Cc,  Cc,   Cc * Cc,   1.f);

    // transpose interaction matrix (causal tiles only)
    dim3 gT(Tt / 32, Tt / 8, Bb);
    transpose_bias<<<gT, 256>>>(inter, biasT);

    // merged down-projection: [4096,1024] @ [1024,512] -> kv_down|q_down
    dim3 gDown(512 / 128, NROW / 128);
    gemm_tc<<<gDown, 256, GEMM_SMEM>>>(xt, wdown, down, 512, Cc, Cc, 512, 512,
                                       nullptr, 1);

    // merged kv up-projection: [4096,256] @ [256,2048] -> k|v
    dim3 gKV(2048 / 128, NROW / 128);
    gemm_tc<<<gKV, 256, GEMM_SMEM>>>(down, wkvup, kv, 2048, Ll, 512, 2048, 2048,
                                     nullptr, 1);

    // q up-projection: [4096,256] @ [256,1024] (weights pre-scaled)
    dim3 gQ(Cc / 128, NROW / 128);
    gemm_tc<<<gQ, 256, GEMM_SMEM>>>(down + 256, wqc, q, Cc, Ll, 512, Cc, Cc,
                                    nullptr, 1);

    // tensor-core flash attention: 128q x 64k tiles
    dim3 gAttn(Tt / BQ, Hh, Bb);
    attn_tc<<<gAttn, 256, ATTN_SMEM>>>(q, Cc, kv, kv + 1024, 2048, biasT,
                                       pmask, ctx);

    // output projection with bias (final: full fp32)
    dim3 gProj(Cc / 128, NROW / 128);
    gemm_tc<<<gProj, 256, GEMM_SMEM>>>(ctx, wproj, out, Cc, Cc, Cc, Cc, Cc,
                                       b_proj, 0);
}

// round 14
// speedup vs baseline: 5.0314x; 1.0269x over previous
#include <cuda_runtime.h>
#include <cuda_bf16.h>
#include <math.h>
#include <stdint.h>

// Problem constants
#define Bb 4
#define Tt 1024
#define Cc 1024
#define Hh 16
#define Ll 256
#define Dd 64
#define NROW (Bb*Tt)   // 4096

// Scratch (allocation-free: __device__ globals)
__device__ float g_xt    [NROW * Cc];          // tf32(x)
__device__ float g_Wdown [Cc * 512];           // tf32(W_ckv) | tf32(W_cq)
__device__ float g_Wkvup [Ll * 2048];          // tf32(W_kc) | tf32(W_vc)
__device__ float g_Wqc   [Ll * Cc];            // tf32(W_qc) * 0.125
__device__ float g_Wproj [Cc * Cc];            // tf32(W_proj)
__device__ float g_down  [NROW * 512];         // kv_down | q_down  (tf32)
__device__ float g_kv    [NROW * 2048];        // k | v  (tf32)
__device__ float g_q     [NROW * Cc];          // q (tf32, pre-scaled)
__device__ float g_ctx   [NROW * Cc];
__device__ float g_biasT [(size_t)Bb * Hh * Tt * Tt];   // [b][h][q][k]

// ---------------------------------------------------------------------------
// tf32 helpers
// ---------------------------------------------------------------------------
__device__ __forceinline__ float ftf32(float x) {
    float r;
    asm("cvt.rna.tf32.f32 %0, %1;" : "=f"(r) : "f"(x));
    return r;
}

__device__ __forceinline__ void mma_tf32(
    float& c0, float& c1, float& c2, float& c3,
    float a0, float a1, float a2, float a3,
    float b0, float b1)
{
    asm volatile(
        "mma.sync.aligned.m16n8k8.row.col.f32.tf32.tf32.f32 "
        "{%0,%1,%2,%3},{%4,%5,%6,%7},{%8,%9},{%0,%1,%2,%3};\n"
        : "+f"(c0), "+f"(c1), "+f"(c2), "+f"(c3)
        : "r"(__float_as_uint(a0)), "r"(__float_as_uint(a1)),
          "r"(__float_as_uint(a2)), "r"(__float_as_uint(a3)),
          "r"(__float_as_uint(b0)), "r"(__float_as_uint(b1)));
}

__device__ __forceinline__ void cpasync16(uint32_t saddr, const void* gptr) {
    asm volatile("cp.async.cg.shared.global [%0], [%1], 16;\n"
                 :: "r"(saddr), "l"(gptr));
}
__device__ __forceinline__ void cp_commit() {
    asm volatile("cp.async.commit_group;\n");
}
template<int NW>
__device__ __forceinline__ void cp_wait() {
    asm volatile("cp.async.wait_group %0;\n" :: "n"(NW));
}

// ---------------------------------------------------------------------------
// Batched tf32 rounding: one launch for all inputs/weights.
// Segment s covers flat float4 indices [end[s-1], end[s]).
// ---------------------------------------------------------------------------
struct CvtSeg {
    const float* in; float* out;
    int cols4; int ldout; int end; float scale;
};
struct CvtArgs { CvtSeg s[7]; };

__global__ __launch_bounds__(256) void cvt_batched(CvtArgs a)
{
    int i = blockIdx.x * 256 + threadIdx.x;
    if (i >= a.s[6].end) return;
    int seg = 0, start = 0;
    #pragma unroll
    for (int j = 0; j < 6; j++)
        if (i >= a.s[j].end) { seg = j + 1; start = a.s[j].end; }
    CvtSeg d = a.s[seg];
    int local = i - start;
    int r = local / d.cols4;
    int c = (local - r * d.cols4) * 4;
    float4 v = *(const float4*)&d.in[(size_t)r * (d.cols4 * 4) + c];
    v.x = ftf32(v.x) * d.scale; v.y = ftf32(v.y) * d.scale;
    v.z = ftf32(v.z) * d.scale; v.w = ftf32(v.w) * d.scale;
    *(float4*)&d.out[(size_t)r * d.ldout + c] = v;
}

// ---------------------------------------------------------------------------
// Tensor-core GEMM (inputs pre-rounded tf32): C[M,N] = A@B (+bias)
// Block 128x128, 256 threads, 8 warps of 32x64. K-step 32, 3-stage cp.async.
// cvt_out != 0 -> RNA-round outputs to tf32.
// ---------------------------------------------------------------------------
#define AST 36
#define BST 136
#define NST 3
#define SA_FL (128*AST)
#define SB_FL (32*BST)
#define STG_FL (SA_FL + SB_FL)
#define GEMM_SMEM (NST * STG_FL * 4)   // 107520 B

__global__ __launch_bounds__(256, 2) void gemm_tc(
    const float* __restrict__ A, const float* __restrict__ B,
    float* __restrict__ C, int N, int K, int lda, int ldb, int ldc,
    const float* __restrict__ bias, int cvt_out)
{
    extern __shared__ float gsm[];

    const int tid  = threadIdx.x;
    const int warp = tid >> 5;
    const int lane = tid & 31;
    const int g    = lane >> 2;
    const int tig  = lane & 3;
    const int wm   = (warp & 3) * 32;
    const int wn   = (warp >> 2) * 64;
    const int bm   = blockIdx.y * 128;
    const int bn   = blockIdx.x * 128;

    const int arow = tid >> 1;            // 0..127
    const int acb  = (tid & 1) * 8;       // 0 or 8 (also +16)
    const int brow = tid >> 4;            // 0..15  (also +16)
    const int bnc  = (tid & 15) * 8;

    uint32_t sAb = (uint32_t)__cvta_generic_to_shared(&gsm[arow * AST + acb]);
    uint32_t sBb = (uint32_t)__cvta_generic_to_shared(
                       &gsm[SA_FL + brow * BST + bnc]);

    const float* gA = A + (size_t)(bm + arow) * lda + acb;
    const float* gB = B + (size_t)brow * ldb + bn + bnc;

    auto load_stage = [&](int stg, int k0) {
        uint32_t dA = sAb + stg * STG_FL * 4;
        uint32_t dB = sBb + stg * STG_FL * 4;
        const float* pA = gA + k0;
        const float* pB = gB + (size_t)k0 * ldb;
        cpasync16(dA,      pA);
        cpasync16(dA + 16, pA + 4);
        cpasync16(dA + 64, pA + 16);
        cpasync16(dA + 80, pA + 20);
        cpasync16(dB,      pB);
        cpasync16(dB + 16, pB + 4);
        cpasync16(dB + 16*BST*4,      pB + (size_t)16 * ldb);
        cpasync16(dB + 16*BST*4 + 16, pB + (size_t)16 * ldb + 4);
    };

    const int nIter = K / 32;
    #pragma unroll
    for (int p = 0; p < NST - 1; p++) {
        if (p < nIter) load_stage(p, p * 32);
        cp_commit();
    }

    float acc[2][8][4];
    #pragma unroll
    for (int tm = 0; tm < 2; tm++)
        #pragma unroll
        for (int tn = 0; tn < 8; tn++)
            #pragma unroll
            for (int j = 0; j < 4; j++) acc[tm][tn][j] = 0.f;

    for (int it = 0; it < nIter; it++) {
        int pre = it + NST - 1;
        if (pre < nIter) load_stage(pre % NST, pre * 32);
        cp_commit();
        cp_wait<NST - 1>();
        __syncthreads();

        const float* Ap = gsm + (it % NST) * STG_FL;
        const float* Bp = Ap + SA_FL;
        #pragma unroll
        for (int kc = 0; kc < 32; kc += 8) {
            float a[2][4];
            #pragma unroll
            for (int tm = 0; tm < 2; tm++) {
                int m = wm + tm * 16;
                a[tm][0] = Ap[(m + g)     * AST + kc + tig];
                a[tm][1] = Ap[(m + g + 8) * AST + kc + tig];
                a[tm][2] = Ap[(m + g)     * AST + kc + tig + 4];
                a[tm][3] = Ap[(m + g + 8) * AST + kc + tig + 4];
            }
            #pragma unroll
            for (int tn = 0; tn < 8; tn++) {
                float b0 = Bp[(kc + tig)     * BST + wn + tn * 8 + g];
                float b1 = Bp[(kc + tig + 4) * BST + wn + tn * 8 + g];
                mma_tf32(acc[0][tn][0], acc[0][tn][1], acc[0][tn][2], acc[0][tn][3],
                         a[0][0], a[0][1], a[0][2], a[0][3], b0, b1);
                mma_tf32(acc[1][tn][0], acc[1][tn][1], acc[1][tn][2], acc[1][tn][3],
                         a[1][0], a[1][1], a[1][2], a[1][3], b0, b1);
            }
        }
        __syncthreads();
    }

    #pragma unroll
    for (int tn = 0; tn < 8; tn++) {
        int col = bn + wn + tn * 8 + 2 * tig;
        float2 bv = {0.f, 0.f};
        if (bias) bv = *(const float2*)&bias[col];
        #pragma unroll
        for (int tm = 0; tm < 2; tm++) {
            int r0 = bm + wm + tm * 16 + g;
            float2 w0 = {acc[tm][tn][0] + bv.x, acc[tm][tn][1] + bv.y};
            float2 w1 = {acc[tm][tn][2] + bv.x, acc[tm][tn][3] + bv.y};
            if (cvt_out) {
                w0.x = ftf32(w0.x); w0.y = ftf32(w0.y);
                w1.x = ftf32(w1.x); w1.y = ftf32(w1.y);
            }
            *(float2*)&C[(size_t)r0 * ldc + col]       = w0;
            *(float2*)&C[(size_t)(r0 + 8) * ldc + col] = w1;
        }
    }
}

// ---------------------------------------------------------------------------
// Transpose interaction matrix: in[b][k][q][h] -> out[b][h][q][k]
// Causal skip: tiles strictly above the 64-diagonal never read -> stay zero.
// ---------------------------------------------------------------------------
__global__ __launch_bounds__(256) void transpose_bias(
    const float* __restrict__ in, float* __restrict__ out)
{
    __shared__ float tile[32 * 129];
    const int k0 = blockIdx.x * 32;
    const int q0 = blockIdx.y * 8;
    const int b  = blockIdx.z;

    if ((k0 >> 6) > (q0 >> 6)) return;

    const size_t ibase = ((size_t)(b * Tt + k0) * Tt + q0) * Hh;
    #pragma unroll
    for (int it = 0; it < 16; it++) {
        int t  = it * 256 + threadIdx.x;
        int kk = t >> 7;
        int r  = t & 127;
        tile[kk * 129 + r] = in[ibase + (size_t)kk * (Tt * Hh) + r];
    }
    __syncthreads();
    #pragma unroll
    for (int it = 0; it < 16; it++) {
        int t  = it * 256 + threadIdx.x;
        int kk = t & 31;
        int o  = t >> 5;
        int h  = o >> 3;
        int qq = o & 7;
        out[((size_t)(b * Hh + h) * Tt + q0 + qq) * Tt + k0 + kk] =
            tile[kk * 129 + qq * 16 + h];
    }
}

// ---------------------------------------------------------------------------
// Tensor-core flash attention (tf32 mma.sync.m16n8k8).
// 256 threads / 8 warps; tile 128q x 64k; warp w owns q rows [16w,16w+16).
// Warp-uniform skip of fully-causally-masked k-tiles.
// ---------------------------------------------------------------------------
#define BQ 128
#define QS 68
#define PS 68
#define KS 68
#define VS 72
#define ATTN_SMEM ((BQ*QS + BQ*PS + 64*KS + 64*VS) * 4)   // 105472 B

__global__ __launch_bounds__(256, 2) void attn_tc(
    const float* __restrict__ Qm, int ldq,
    const float* __restrict__ Km, const float* __restrict__ Vm, int ldkv,
    const float* __restrict__ biasT, const int* __restrict__ pad,
    float* __restrict__ ctx)
{
    extern __shared__ float sm[];
    float* Qs = sm;                    // [128][QS]
    float* Ps = Qs + BQ * QS;          // [128][PS]
    float* Ks = Ps + BQ * PS;          // [64][KS]
    float* Vs = Ks + 64 * KS;          // [64][VS]

    const int qt = (gridDim.x - 1) - blockIdx.x;   // heavy tiles first
    const int h  = blockIdx.y;
    const int b  = blockIdx.z;
    const int tid  = threadIdx.x;
    const int warp = tid >> 5;
    const int lane = tid & 31;
    const int g    = lane >> 2;
    const int tig  = lane & 3;

    const int r0  = warp * 16 + g;          // local q row (c0/c1)
    const int qg0 = qt * BQ + r0;
    const int qg1 = qg0 + 8;
    const int qwmax = qt * BQ + warp * 16 + 15;   // warp's max global q row

    const float* bias_bh = biasT + (size_t)(b * Hh + h) * Tt * Tt;
    const int pm0 = pad[b * Tt + qg0];
    const int pm1 = pad[b * Tt + qg1];

    uint32_t qsB = (uint32_t)__cvta_generic_to_shared(Qs);
    uint32_t ksB = (uint32_t)__cvta_generic_to_shared(Ks);
    uint32_t vsB = (uint32_t)__cvta_generic_to_shared(Vs);

    // async-load Q tile (128x64); completion covered by iter-0 wait
    for (int i = tid; i < BQ * 16; i += 256) {
        int row = i >> 4, c4 = (i & 15) * 4;
        cpasync16(qsB + (row * QS + c4) * 4,
                  &Qm[(size_t)(b * Tt + qt * BQ + row) * ldq + h * Dd + c4]);
    }
    cp_commit();

    float m0 = -INFINITY, m1 = -INFINITY, l0 = 0.f, l1 = 0.f;
    float o[8][4];
    #pragma unroll
    for (int n = 0; n < 8; n++)
        #pragma unroll
        for (int j = 0; j < 4; j++) o[n][j] = 0.f;

    const int ktmax = 2 * qt + 1;
    for (int kt = 0; kt <= ktmax; kt++) {
        __syncthreads();   // prev iter done reading Ks/Vs
        for (int i = tid; i < 64 * 16; i += 256) {
            int row = i >> 4, c4 = (i & 15) * 4;
            size_t gofs = (size_t)(b * Tt + kt * 64 + row) * ldkv + h * Dd + c4;
            cpasync16(ksB + (row * KS + c4) * 4, Km + gofs);
            cpasync16(vsB + (row * VS + c4) * 4, Vm + gofs);
        }
        cp_commit();
        cp_wait<0>();
        __syncthreads();   // K/V (and Q on iter 0) ready

        const int kbase = kt * 64;
        if (kbase <= qwmax) {   // warp-uniform: skip fully-masked tiles
            // ---- S = Q @ K^T ----
            float s[8][4];
            #pragma unroll
            for (int n = 0; n < 8; n++)
                #pragma unroll
                for (int j = 0; j < 4; j++) s[n][j] = 0.f;

            #pragma unroll
            for (int kc = 0; kc < 64; kc += 8) {
                float a0 = Qs[(r0)     * QS + kc + tig];
                float a1 = Qs[(r0 + 8) * QS + kc + tig];
                float a2 = Qs[(r0)     * QS + kc + tig + 4];
                float a3 = Qs[(r0 + 8) * QS + kc + tig + 4];
                #pragma unroll
                for (int n = 0; n < 8; n++) {
                    float b0 = Ks[(n * 8 + g) * KS + kc + tig];
                    float b1 = Ks[(n * 8 + g) * KS + kc + tig + 4];
                    mma_tf32(s[n][0], s[n][1], s[n][2], s[n][3],
                             a0, a1, a2, a3, b0, b1);
                }
            }

            // ---- mask + bias ----
            const bool need0 = (kbase + 63) > qg0;
            const bool need1 = (kbase + 63) > qg1;
            #pragma unroll
            for (int n = 0; n < 8; n++) {
                int kg = kbase + n * 8 + 2 * tig;
                float2 bi0 = *(const float2*)&bias_bh[(size_t)qg0 * Tt + kg];
                float2 bi1 = *(const float2*)&bias_bh[(size_t)qg1 * Tt + kg];
                s[n][0] = (pm0 ? s[n][0] : -1e9f) + bi0.x;
                s[n][1] = (pm0 ? s[n][1] : -1e9f) + bi0.y;
                s[n][2] = (pm1 ? s[n][2] : -1e9f) + bi1.x;
                s[n][3] = (pm1 ? s[n][3] : -1e9f) + bi1.y;
                if (need0) {
                    if (kg     > qg0) s[n][0] = -INFINITY;
                    if (kg + 1 > qg0) s[n][1] = -INFINITY;
                }
                if (need1) {
                    if (kg     > qg1) s[n][2] = -INFINITY;
                    if (kg + 1 > qg1) s[n][3] = -INFINITY;
                }
            }

            // ---- online softmax (quad reduce over lanes xor 1,2) ----
            float rm0 = -INFINITY, rm1 = -INFINITY;
            #pragma unroll
            for (int n = 0; n < 8; n++) {
                rm0 = fmaxf(rm0, fmaxf(s[n][0], s[n][1]));
                rm1 = fmaxf(rm1, fmaxf(s[n][2], s[n][3]));
            }
            rm0 = fmaxf(rm0, __shfl_xor_sync(0xffffffffu, rm0, 1));
            rm0 = fmaxf(rm0, __shfl_xor_sync(0xffffffffu, rm0, 2));
            rm1 = fmaxf(rm1, __shfl_xor_sync(0xffffffffu, rm1, 1));
            rm1 = fmaxf(rm1, __shfl_xor_sync(0xffffffffu, rm1, 2));

            float mn0 = fmaxf(m0, rm0);
            float mn1 = fmaxf(m1, rm1);
            float al0 = __expf(m0 - mn0);
            float al1 = __expf(m1 - mn1);
            m0 = mn0; m1 = mn1;

            float rs0 = 0.f, rs1 = 0.f;
            #pragma unroll
            for (int n = 0; n < 8; n++) {
                s[n][0] = __expf(s[n][0] - mn0);
                s[n][1] = __expf(s[n][1] - mn0);
                s[n][2] = __expf(s[n][2] - mn1);
                s[n][3] = __expf(s[n][3] - mn1);
                rs0 += s[n][0] + s[n][1];
                rs1 += s[n][2] + s[n][3];
            }
            rs0 += __shfl_xor_sync(0xffffffffu, rs0, 1);
            rs0 += __shfl_xor_sync(0xffffffffu, rs0, 2);
            rs1 += __shfl_xor_sync(0xffffffffu, rs1, 1);
            rs1 += __shfl_xor_sync(0xffffffffu, rs1, 2);
            l0 = l0 * al0 + rs0;
            l1 = l1 * al1 + rs1;

            #pragma unroll
            for (int n = 0; n < 8; n++) {
                o[n][0] *= al0; o[n][1] *= al0;
                o[n][2] *= al1; o[n][3] *= al1;
            }

            // ---- P relayout: warp-private rows, warp sync only ----
            #pragma unroll
            for (int n = 0; n < 8; n++) {
                Ps[(r0)     * PS + n * 8 + 2 * tig]     = ftf32(s[n][0]);
                Ps[(r0)     * PS + n * 8 + 2 * tig + 1] = ftf32(s[n][1]);
                Ps[(r0 + 8) * PS + n * 8 + 2 * tig]     = ftf32(s[n][2]);
                Ps[(r0 + 8) * PS + n * 8 + 2 * tig + 1] = ftf32(s[n][3]);
            }
            __syncwarp();

            // ---- O += P @ V ----
            #pragma unroll
            for (int kc = 0; kc < 64; kc += 8) {
                float a0 = Ps[(r0)     * PS + kc + tig];
                float a1 = Ps[(r0 + 8) * PS + kc + tig];
                float a2 = Ps[(r0)     * PS + kc + tig + 4];
                float a3 = Ps[(r0 + 8) * PS + kc + tig + 4];
                #pragma unroll
                for (int n = 0; n < 8; n++) {
                    float b0 = Vs[(kc + tig)     * VS + n * 8 + g];
                    float b1 = Vs[(kc + tig + 4) * VS + n * 8 + g];
                    mma_tf32(o[n][0], o[n][1], o[n][2], o[n][3],
                             a0, a1, a2, a3, b0, b1);
                }
            }
        }
    }

    // epilogue: normalize, RNA-round to tf32 (ctx feeds proj GEMM A-side)
    float inv0 = 1.f / l0;
    float inv1 = 1.f / l1;
    #pragma unroll
    for (int n = 0; n < 8; n++) {
        int d = n * 8 + 2 * tig;
        float2 w0 = {ftf32(o[n][0] * inv0), ftf32(o[n][1] * inv0)};
        float2 w1 = {ftf32(o[n][2] * inv1), ftf32(o[n][3] * inv1)};
        *(float2*)&ctx[(size_t)(b * Tt + qg0) * Cc + h * Dd + d] = w0;
        *(float2*)&ctx[(size_t)(b * Tt + qg1) * Cc + h * Dd + d] = w1;
    }
}

// ---------------------------------------------------------------------------
extern "C" void kernel_launch(void* const* d_in, const int* in_sizes, int n_in,
                              void* d_out, int out_size)
{
    const float* x      = (const float*)d_in[0];
    const int*   pmask  = (const int*)  d_in[1];
    const float* inter  = (const float*)d_in[2];
    const float* W_ckv  = (const float*)d_in[3];
    const float* W_cq   = (const float*)d_in[4];
    const float* W_kc   = (const float*)d_in[5];
    const float* W_qc   = (const float*)d_in[6];
    const float* W_vc   = (const float*)d_in[7];
    const float* W_proj = (const float*)d_in[8];
    const float* b_proj = (const float*)d_in[9];
    float* out = (float*)d_out;

    float *xt, *wdown, *wkvup, *wqc, *wproj;
    float *down, *kv, *q, *ctx, *biasT;
    cudaGetSymbolAddress((void**)&xt,    g_xt);
    cudaGetSymbolAddress((void**)&wdown, g_Wdown);
    cudaGetSymbolAddress((void**)&wkvup, g_Wkvup);
    cudaGetSymbolAddress((void**)&wqc,   g_Wqc);
    cudaGetSymbolAddress((void**)&wproj, g_Wproj);
    cudaGetSymbolAddress((void**)&down,  g_down);
    cudaGetSymbolAddress((void**)&kv,    g_kv);
    cudaGetSymbolAddress((void**)&q,     g_q);
    cudaGetSymbolAddress((void**)&ctx,   g_ctx);
    cudaGetSymbolAddress((void**)&biasT, g_biasT);

    cudaFuncSetAttribute(gemm_tc, cudaFuncAttributeMaxDynamicSharedMemorySize,
                         GEMM_SMEM);
    cudaFuncSetAttribute(attn_tc, cudaFuncAttributeMaxDynamicSharedMemorySize,
                         ATTN_SMEM);

    // one batched tf32-rounding launch for all inputs/weights
    CvtArgs ca;
    int e = 0;
    auto seg = [&](int idx, const float* in, float* outp, int cols, int ldout,
                   int n, float scale) {
        e += n / 4;
        ca.s[idx] = {in, outp, cols / 4, ldout, e, scale};
    };
    seg(0, x,      xt,           Cc, Cc,   NROW * Cc, 1.f);
    seg(1, W_ckv,  wdown,        Ll, 512,  Cc * Ll,   1.f);
    seg(2, W_cq,   wdown + 256,  Ll, 512,  Cc * Ll,   1.f);
    seg(3, W_kc,   wkvup,        Cc, 2048, Ll * Cc,   1.f);
    seg(4, W_vc,   wkvup + 1024, Cc, 2048, Ll * Cc,   1.f);
    seg(5, W_qc,   wqc,          Cc, Cc,   Ll * Cc,   0.125f);
    seg(6, W_proj, wproj,        Cc, Cc,   Cc * Cc,   1.f);
    cvt_batched<<<(e + 255) / 256, 256>>>(ca);                        // launch 0

    // transpose interaction matrix (causal tiles only)
    dim3 gT(Tt / 32, Tt / 8, Bb);
    transpose_bias<<<gT, 256>>>(inter, biasT);                        // launch 1

    // merged down-projection: [4096,1024] @ [1024,512] -> kv_down|q_down
    dim3 gDown(512 / 128, NROW / 128);
    gemm_tc<<<gDown, 256, GEMM_SMEM>>>(xt, wdown, down, 512, Cc, Cc, 512, 512,
                                       nullptr, 1);                   // launch 2

    // merged kv up-projection: [4096,256] @ [256,2048] -> k|v
    dim3 gKV(2048 / 128, NROW / 128);
    gemm_tc<<<gKV, 256, GEMM_SMEM>>>(down, wkvup, kv, 2048, Ll, 512, 2048, 2048,
                                     nullptr, 1);                     // launch 3

    // q up-projection: [4096,256] @ [256,1024] (weights pre-scaled)
    dim3 gQ(Cc / 128, NROW / 128);
    gemm_tc<<<gQ, 256, GEMM_SMEM>>>(down + 256, wqc, q, Cc, Ll, 512, Cc, Cc,
                                    nullptr, 1);                      // launch 4

    // tensor-core flash attention: 128q x 64k tiles   (launch 5 -> profiled)
    dim3 gAttn(Tt / BQ, Hh, Bb);
    attn_tc<<<gAttn, 256, ATTN_SMEM>>>(q, Cc, kv, kv + 1024, 2048, biasT,
                                       pmask, ctx);

    // output projection with bias (final: full fp32)
    dim3 gProj(Cc / 128, NROW / 128);
    gemm_tc<<<gProj, 256, GEMM_SMEM>>>(ctx, wproj, out, Cc, Cc, Cc, Cc, Cc,
                                       b_proj, 0);                    // launch 6
}

// round 16
// speedup vs baseline: 5.0719x; 1.0080x over previous
#include <cuda_runtime.h>
#include <cuda_bf16.h>
#include <math.h>
#include <stdint.h>

// Problem constants
#define Bb 4
#define Tt 1024
#define Cc 1024
#define Hh 16
#define Ll 256
#define Dd 64
#define NROW (Bb*Tt)   // 4096

// Scratch (allocation-free: __device__ globals)
__device__ float g_xt    [NROW * Cc];          // tf32(x)
__device__ float g_Wdown [Cc * 512];           // tf32(W_ckv) | tf32(W_cq)
__device__ float g_Wkvup [Ll * 2048];          // tf32(W_kc) | tf32(W_vc)
__device__ float g_Wqc   [Ll * Cc];            // tf32(W_qc) * 0.125
__device__ float g_Wproj [Cc * Cc];            // tf32(W_proj)
__device__ float g_down  [NROW * 512];         // kv_down | q_down  (tf32)
__device__ float g_kv    [NROW * 2048];        // k | v  (tf32)
__device__ float g_q     [NROW * Cc];          // q (tf32, pre-scaled, pad-zeroed)
__device__ float g_ctx   [NROW * Cc];
__device__ float g_biasT [(size_t)Bb * Hh * Tt * Tt];   // [b][h][q][k]

// ---------------------------------------------------------------------------
// tf32 helpers
// ---------------------------------------------------------------------------
__device__ __forceinline__ float ftf32(float x) {
    float r;
    asm("cvt.rna.tf32.f32 %0, %1;" : "=f"(r) : "f"(x));
    return r;
}

__device__ __forceinline__ void mma_tf32(
    float& c0, float& c1, float& c2, float& c3,
    float a0, float a1, float a2, float a3,
    float b0, float b1)
{
    asm volatile(
        "mma.sync.aligned.m16n8k8.row.col.f32.tf32.tf32.f32 "
        "{%0,%1,%2,%3},{%4,%5,%6,%7},{%8,%9},{%0,%1,%2,%3};\n"
        : "+f"(c0), "+f"(c1), "+f"(c2), "+f"(c3)
        : "r"(__float_as_uint(a0)), "r"(__float_as_uint(a1)),
          "r"(__float_as_uint(a2)), "r"(__float_as_uint(a3)),
          "r"(__float_as_uint(b0)), "r"(__float_as_uint(b1)));
}

__device__ __forceinline__ void cpasync16(uint32_t saddr, const void* gptr) {
    asm volatile("cp.async.cg.shared.global [%0], [%1], 16;\n"
                 :: "r"(saddr), "l"(gptr));
}
__device__ __forceinline__ void cp_commit() {
    asm volatile("cp.async.commit_group;\n");
}
template<int NW>
__device__ __forceinline__ void cp_wait() {
    asm volatile("cp.async.wait_group %0;\n" :: "n"(NW));
}

// ---------------------------------------------------------------------------
// Batched tf32 rounding: one launch for all inputs/weights.
// ---------------------------------------------------------------------------
struct CvtSeg {
    const float* in; float* out;
    int cols4; int ldout; int end; float scale;
};
struct CvtArgs { CvtSeg s[7]; };

__global__ __launch_bounds__(256) void cvt_batched(CvtArgs a)
{
    int i = blockIdx.x * 256 + threadIdx.x;
    if (i >= a.s[6].end) return;
    int seg = 0, start = 0;
    #pragma unroll
    for (int j = 0; j < 6; j++)
        if (i >= a.s[j].end) { seg = j + 1; start = a.s[j].end; }
    CvtSeg d = a.s[seg];
    int local = i - start;
    int r = local / d.cols4;
    int c = (local - r * d.cols4) * 4;
    float4 v = *(const float4*)&d.in[(size_t)r * (d.cols4 * 4) + c];
    v.x = ftf32(v.x) * d.scale; v.y = ftf32(v.y) * d.scale;
    v.z = ftf32(v.z) * d.scale; v.w = ftf32(v.w) * d.scale;
    *(float4*)&d.out[(size_t)r * d.ldout + c] = v;
}

// ---------------------------------------------------------------------------
// Tensor-core GEMM (inputs pre-rounded tf32): C[M,N] = A@B (+bias)
// Block 128x128, 256 threads, 8 warps of 32x64. K-step 32, 3-stage cp.async.
// cvt_out -> RNA-round outputs. rowmask -> multiply output rows by mask (0/1).
// ---------------------------------------------------------------------------
#define AST 36
#define BST 136
#define NST 3
#define SA_FL (128*AST)
#define SB_FL (32*BST)
#define STG_FL (SA_FL + SB_FL)
#define GEMM_SMEM (NST * STG_FL * 4)   // 107520 B

__global__ __launch_bounds__(256, 2) void gemm_tc(
    const float* __restrict__ A, const float* __restrict__ B,
    float* __restrict__ C, int N, int K, int lda, int ldb, int ldc,
    const float* __restrict__ bias, int cvt_out,
    const int* __restrict__ rowmask)
{
    extern __shared__ float gsm[];

    const int tid  = threadIdx.x;
    const int warp = tid >> 5;
    const int lane = tid & 31;
    const int g    = lane >> 2;
    const int tig  = lane & 3;
    const int wm   = (warp & 3) * 32;
    const int wn   = (warp >> 2) * 64;
    const int bm   = blockIdx.y * 128;
    const int bn   = blockIdx.x * 128;

    const int arow = tid >> 1;            // 0..127
    const int acb  = (tid & 1) * 8;       // 0 or 8 (also +16)
    const int brow = tid >> 4;            // 0..15  (also +16)
    const int bnc  = (tid & 15) * 8;

    uint32_t sAb = (uint32_t)__cvta_generic_to_shared(&gsm[arow * AST + acb]);
    uint32_t sBb = (uint32_t)__cvta_generic_to_shared(
                       &gsm[SA_FL + brow * BST + bnc]);

    const float* gA = A + (size_t)(bm + arow) * lda + acb;
    const float* gB = B + (size_t)brow * ldb + bn + bnc;

    auto load_stage = [&](int stg, int k0) {
        uint32_t dA = sAb + stg * STG_FL * 4;
        uint32_t dB = sBb + stg * STG_FL * 4;
        const float* pA = gA + k0;
        const float* pB = gB + (size_t)k0 * ldb;
        cpasync16(dA,      pA);
        cpasync16(dA + 16, pA + 4);
        cpasync16(dA + 64, pA + 16);
        cpasync16(dA + 80, pA + 20);
        cpasync16(dB,      pB);
        cpasync16(dB + 16, pB + 4);
        cpasync16(dB + 16*BST*4,      pB + (size_t)16 * ldb);
        cpasync16(dB + 16*BST*4 + 16, pB + (size_t)16 * ldb + 4);
    };

    const int nIter = K / 32;
    #pragma unroll
    for (int p = 0; p < NST - 1; p++) {
        if (p < nIter) load_stage(p, p * 32);
        cp_commit();
    }

    float acc[2][8][4];
    #pragma unroll
    for (int tm = 0; tm < 2; tm++)
        #pragma unroll
        for (int tn = 0; tn < 8; tn++)
            #pragma unroll
            for (int j = 0; j < 4; j++) acc[tm][tn][j] = 0.f;

    for (int it = 0; it < nIter; it++) {
        int pre = it + NST - 1;
        if (pre < nIter) load_stage(pre % NST, pre * 32);
        cp_commit();
        cp_wait<NST - 1>();
        __syncthreads();

        const float* Ap = gsm + (it % NST) * STG_FL;
        const float* Bp = Ap + SA_FL;
        #pragma unroll
        for (int kc = 0; kc < 32; kc += 8) {
            float a[2][4];
            #pragma unroll
            for (int tm = 0; tm < 2; tm++) {
                int m = wm + tm * 16;
                a[tm][0] = Ap[(m + g)     * AST + kc + tig];
                a[tm][1] = Ap[(m + g + 8) * AST + kc + tig];
                a[tm][2] = Ap[(m + g)     * AST + kc + tig + 4];
                a[tm][3] = Ap[(m + g + 8) * AST + kc + tig + 4];
            }
            #pragma unroll
            for (int tn = 0; tn < 8; tn++) {
                float b0 = Bp[(kc + tig)     * BST + wn + tn * 8 + g];
                float b1 = Bp[(kc + tig + 4) * BST + wn + tn * 8 + g];
                mma_tf32(acc[0][tn][0], acc[0][tn][1], acc[0][tn][2], acc[0][tn][3],
                         a[0][0], a[0][1], a[0][2], a[0][3], b0, b1);
                mma_tf32(acc[1][tn][0], acc[1][tn][1], acc[1][tn][2], acc[1][tn][3],
                         a[1][0], a[1][1], a[1][2], a[1][3], b0, b1);
            }
        }
        __syncthreads();
    }

    #pragma unroll
    for (int tn = 0; tn < 8; tn++) {
        int col = bn + wn + tn * 8 + 2 * tig;
        float2 bv = {0.f, 0.f};
        if (bias) bv = *(const float2*)&bias[col];
        #pragma unroll
        for (int tm = 0; tm < 2; tm++) {
            int r0 = bm + wm + tm * 16 + g;
            float rm0 = 1.f, rm1 = 1.f;
            if (rowmask) {
                rm0 = (float)rowmask[r0];
                rm1 = (float)rowmask[r0 + 8];
            }
            float2 w0 = {(acc[tm][tn][0] + bv.x) * rm0,
                         (acc[tm][tn][1] + bv.y) * rm0};
            float2 w1 = {(acc[tm][tn][2] + bv.x) * rm1,
                         (acc[tm][tn][3] + bv.y) * rm1};
            if (cvt_out) {
                w0.x = ftf32(w0.x); w0.y = ftf32(w0.y);
                w1.x = ftf32(w1.x); w1.y = ftf32(w1.y);
            }
            *(float2*)&C[(size_t)r0 * ldc + col]       = w0;
            *(float2*)&C[(size_t)(r0 + 8) * ldc + col] = w1;
        }
    }
}

// ---------------------------------------------------------------------------
// Transpose interaction matrix: in[b][k][q][h] -> out[b][h][q][k]
// Causal skip: tiles strictly above the 64-diagonal never read -> stay zero.
// ---------------------------------------------------------------------------
__global__ __launch_bounds__(256) void transpose_bias(
    const float* __restrict__ in, float* __restrict__ out)
{
    __shared__ float tile[32 * 129];
    const int k0 = blockIdx.x * 32;
    const int q0 = blockIdx.y * 8;
    const int b  = blockIdx.z;

    if ((k0 >> 6) > (q0 >> 6)) return;

    const size_t ibase = ((size_t)(b * Tt + k0) * Tt + q0) * Hh;
    #pragma unroll
    for (int it = 0; it < 16; it++) {
        int t  = it * 256 + threadIdx.x;
        int kk = t >> 7;
        int r  = t & 127;
        tile[kk * 129 + r] = in[ibase + (size_t)kk * (Tt * Hh) + r];
    }
    __syncthreads();
    #pragma unroll
    for (int it = 0; it < 16; it++) {
        int t  = it * 256 + threadIdx.x;
        int kk = t & 31;
        int o  = t >> 5;
        int h  = o >> 3;
        int qq = o & 7;
        out[((size_t)(b * Hh + h) * Tt + q0 + qq) * Tt + k0 + kk] =
            tile[kk * 129 + qq * 16 + h];
    }
}

// ---------------------------------------------------------------------------
// Tensor-core flash attention (tf32 mma.sync.m16n8k8).
// 256 threads / 8 warps; tile 128q x 64k; warp w owns q rows [16w,16w+16).
// Bias is preloaded into the S accumulator (loads issued before the K/V
// wait -> latency hidden). Padded q rows are zeroed upstream (q-up GEMM
// rowmask), so S = bias for them -> uniform softmax, matching the reference
// (-1e9 + bias rounds to -1e9 in fp32, which also yields uniform rows).
// ---------------------------------------------------------------------------
#define BQ 128
#define QS 68
#define PS 68
#define KS 68
#define VS 72
#define ATTN_SMEM ((BQ*QS + BQ*PS + 64*KS + 64*VS) * 4)   // 105472 B

__global__ __launch_bounds__(256, 2) void attn_tc(
    const float* __restrict__ Qm, int ldq,
    const float* __restrict__ Km, const float* __restrict__ Vm, int ldkv,
    const float* __restrict__ biasT, const int* __restrict__ pad,
    float* __restrict__ ctx)
{
    extern __shared__ float sm[];
    float* Qs = sm;                    // [128][QS]
    float* Ps = Qs + BQ * QS;          // [128][PS]
    float* Ks = Ps + BQ * PS;          // [64][KS]
    float* Vs = Ks + 64 * KS;          // [64][VS]

    const int qt = (gridDim.x - 1) - blockIdx.x;   // heavy tiles first
    const int h  = blockIdx.y;
    const int b  = blockIdx.z;
    const int tid  = threadIdx.x;
    const int warp = tid >> 5;
    const int lane = tid & 31;
    const int g    = lane >> 2;
    const int tig  = lane & 3;

    const int r0  = warp * 16 + g;          // local q row (c0/c1)
    const int qg0 = qt * BQ + r0;
    const int qg1 = qg0 + 8;
    const int qwmax = qt * BQ + warp * 16 + 15;   // warp's max global q row

    const float* bias_bh = biasT + (size_t)(b * Hh + h) * Tt * Tt;
    const float fm0 = (float)pad[b * Tt + qg0];   // 0 or 1
    const float fm1 = (float)pad[b * Tt + qg1];

    uint32_t qsB = (uint32_t)__cvta_generic_to_shared(Qs);
    uint32_t ksB = (uint32_t)__cvta_generic_to_shared(Ks);
    uint32_t vsB = (uint32_t)__cvta_generic_to_shared(Vs);

    // async-load Q tile (128x64); completion covered by iter-0 wait
    for (int i = tid; i < BQ * 16; i += 256) {
        int row = i >> 4, c4 = (i & 15) * 4;
        cpasync16(qsB + (row * QS + c4) * 4,
                  &Qm[(size_t)(b * Tt + qt * BQ + row) * ldq + h * Dd + c4]);
    }
    cp_commit();

    float m0 = -INFINITY, m1 = -INFINITY, l0 = 0.f, l1 = 0.f;
    float o[8][4];
    #pragma unroll
    for (int n = 0; n < 8; n++)
        #pragma unroll
        for (int j = 0; j < 4; j++) o[n][j] = 0.f;

    const int ktmax = 2 * qt + 1;
    for (int kt = 0; kt <= ktmax; kt++) {
        __syncthreads();   // prev iter done reading Ks/Vs
        for (int i = tid; i < 64 * 16; i += 256) {
            int row = i >> 4, c4 = (i & 15) * 4;
            size_t gofs = (size_t)(b * Tt + kt * 64 + row) * ldkv + h * Dd + c4;
            cpasync16(ksB + (row * KS + c4) * 4, Km + gofs);
            cpasync16(vsB + (row * VS + c4) * 4, Vm + gofs);
        }
        cp_commit();

        const int kbase = kt * 64;
        const bool active = (kbase <= qwmax);

        // bias preload into accumulator init; issued BEFORE the K/V wait so
        // gmem latency hides under it. Padded rows get 0 (uniform softmax).
        float s[8][4];
        if (active) {
            #pragma unroll
            for (int n = 0; n < 8; n++) {
                int kg = kbase + n * 8 + 2 * tig;
                float2 bi0 = *(const float2*)&bias_bh[(size_t)qg0 * Tt + kg];
                float2 bi1 = *(const float2*)&bias_bh[(size_t)qg1 * Tt + kg];
                s[n][0] = bi0.x * fm0;
                s[n][1] = bi0.y * fm0;
                s[n][2] = bi1.x * fm1;
                s[n][3] = bi1.y * fm1;
            }
        }

        cp_wait<0>();
        __syncthreads();   // K/V (and Q on iter 0) ready

        if (active) {   // warp-uniform: skip fully-masked tiles
            // ---- S = bias + Q @ K^T ----
            #pragma unroll
            for (int kc = 0; kc < 64; kc += 8) {
                float a0 = Qs[(r0)     * QS + kc + tig];
                float a1 = Qs[(r0 + 8) * QS + kc + tig];
                float a2 = Qs[(r0)     * QS + kc + tig + 4];
                float a3 = Qs[(r0 + 8) * QS + kc + tig + 4];
                #pragma unroll
                for (int n = 0; n < 8; n++) {
                    float b0 = Ks[(n * 8 + g) * KS + kc + tig];
                    float b1 = Ks[(n * 8 + g) * KS + kc + tig + 4];
                    mma_tf32(s[n][0], s[n][1], s[n][2], s[n][3],
                             a0, a1, a2, a3, b0, b1);
                }
            }

            // ---- causal mask (diag-straddling tiles only) ----
            if ((kbase + 63) > qg0) {
                #pragma unroll
                for (int n = 0; n < 8; n++) {
                    int kg = kbase + n * 8 + 2 * tig;
                    if (kg     > qg0) s[n][0] = -INFINITY;
                    if (kg + 1 > qg0) s[n][1] = -INFINITY;
                }
            }
            if ((kbase + 63) > qg1) {
                #pragma unroll
                for (int n = 0; n < 8; n++) {
                    int kg = kbase + n * 8 + 2 * tig;
                    if (kg     > qg1) s[n][2] = -INFINITY;
                    if (kg + 1 > qg1) s[n][3] = -INFINITY;
                }
            }

            // ---- online softmax (quad reduce over lanes xor 1,2) ----
            float rm0 = -INFINITY, rm1 = -INFINITY;
            #pragma unroll
            for (int n = 0; n < 8; n++) {
                rm0 = fmaxf(rm0, fmaxf(s[n][0], s[n][1]));
                rm1 = fmaxf(rm1, fmaxf(s[n][2], s[n][3]));
            }
            rm0 = fmaxf(rm0, __shfl_xor_sync(0xffffffffu, rm0, 1));
            rm0 = fmaxf(rm0, __shfl_xor_sync(0xffffffffu, rm0, 2));
            rm1 = fmaxf(rm1, __shfl_xor_sync(0xffffffffu, rm1, 1));
            rm1 = fmaxf(rm1, __shfl_xor_sync(0xffffffffu, rm1, 2));

            float mn0 = fmaxf(m0, rm0);
            float mn1 = fmaxf(m1, rm1);
            float al0 = __expf(m0 - mn0);
            float al1 = __expf(m1 - mn1);
            m0 = mn0; m1 = mn1;

            float rs0 = 0.f, rs1 = 0.f;
            #pragma unroll
            for (int n = 0; n < 8; n++) {
                s[n][0] = __expf(s[n][0] - mn0);
                s[n][1] = __expf(s[n][1] - mn0);
                s[n][2] = __expf(s[n][2] - mn1);
                s[n][3] = __expf(s[n][3] - mn1);
                rs0 += s[n][0] + s[n][1];
                rs1 += s[n][2] + s[n][3];
            }
            rs0 += __shfl_xor_sync(0xffffffffu, rs0, 1);
            rs0 += __shfl_xor_sync(0xffffffffu, rs0, 2);
            rs1 += __shfl_xor_sync(0xffffffffu, rs1, 1);
            rs1 += __shfl_xor_sync(0xffffffffu, rs1, 2);
            l0 = l0 * al0 + rs0;
            l1 = l1 * al1 + rs1;

            #pragma unroll
            for (int n = 0; n < 8; n++) {
                o[n][0] *= al0; o[n][1] *= al0;
                o[n][2] *= al1; o[n][3] *= al1;
            }

            // ---- P relayout: warp-private rows, warp sync only ----
            #pragma unroll
            for (int n = 0; n < 8; n++) {
                Ps[(r0)     * PS + n * 8 + 2 * tig]     = ftf32(s[n][0]);
                Ps[(r0)     * PS + n * 8 + 2 * tig + 1] = ftf32(s[n][1]);
                Ps[(r0 + 8) * PS + n * 8 + 2 * tig]     = ftf32(s[n][2]);
                Ps[(r0 + 8) * PS + n * 8 + 2 * tig + 1] = ftf32(s[n][3]);
            }
            __syncwarp();

            // ---- O += P @ V ----
            #pragma unroll
            for (int kc = 0; kc < 64; kc += 8) {
                float a0 = Ps[(r0)     * PS + kc + tig];
                float a1 = Ps[(r0 + 8) * PS + kc + tig];
                float a2 = Ps[(r0)     * PS + kc + tig + 4];
                float a3 = Ps[(r0 + 8) * PS + kc + tig + 4];
                #pragma unroll
                for (int n = 0; n < 8; n++) {
                    float b0 = Vs[(kc + tig)     * VS + n * 8 + g];
                    float b1 = Vs[(kc + tig + 4) * VS + n * 8 + g];
                    mma_tf32(o[n][0], o[n][1], o[n][2], o[n][3],
                             a0, a1, a2, a3, b0, b1);
                }
            }
        }
    }

    // epilogue: normalize, RNA-round to tf32 (ctx feeds proj GEMM A-side)
    float inv0 = 1.f / l0;
    float inv1 = 1.f / l1;
    #pragma unroll
    for (int n = 0; n < 8; n++) {
        int d = n * 8 + 2 * tig;
        float2 w0 = {ftf32(o[n][0] * inv0), ftf32(o[n][1] * inv0)};
        float2 w1 = {ftf32(o[n][2] * inv1), ftf32(o[n][3] * inv1)};
        *(float2*)&ctx[(size_t)(b * Tt + qg0) * Cc + h * Dd + d] = w0;
        *(float2*)&ctx[(size_t)(b * Tt + qg1) * Cc + h * Dd + d] = w1;
    }
}

// ---------------------------------------------------------------------------
extern "C" void kernel_launch(void* const* d_in, const int* in_sizes, int n_in,
                              void* d_out, int out_size)
{
    const float* x      = (const float*)d_in[0];
    const int*   pmask  = (const int*)  d_in[1];
    const float* inter  = (const float*)d_in[2];
    const float* W_ckv  = (const float*)d_in[3];
    const float* W_cq   = (const float*)d_in[4];
    const float* W_kc   = (const float*)d_in[5];
    const float* W_qc   = (const float*)d_in[6];
    const float* W_vc   = (const float*)d_in[7];
    const float* W_proj = (const float*)d_in[8];
    const float* b_proj = (const float*)d_in[9];
    float* out = (float*)d_out;

    float *xt, *wdown, *wkvup, *wqc, *wproj;
    float *down, *kv, *q, *ctx, *biasT;
    cudaGetSymbolAddress((void**)&xt,    g_xt);
    cudaGetSymbolAddress((void**)&wdown, g_Wdown);
    cudaGetSymbolAddress((void**)&wkvup, g_Wkvup);
    cudaGetSymbolAddress((void**)&wqc,   g_Wqc);
    cudaGetSymbolAddress((void**)&wproj, g_Wproj);
    cudaGetSymbolAddress((void**)&down,  g_down);
    cudaGetSymbolAddress((void**)&kv,    g_kv);
    cudaGetSymbolAddress((void**)&q,     g_q);
    cudaGetSymbolAddress((void**)&ctx,   g_ctx);
    cudaGetSymbolAddress((void**)&biasT, g_biasT);

    cudaFuncSetAttribute(gemm_tc, cudaFuncAttributeMaxDynamicSharedMemorySize,
                         GEMM_SMEM);
    cudaFuncSetAttribute(attn_tc, cudaFuncAttributeMaxDynamicSharedMemorySize,
                         ATTN_SMEM);

    // one batched tf32-rounding launch for all inputs/weights
    CvtArgs ca;
    int e = 0;
    auto seg = [&](int idx, const float* in, float* outp, int cols, int ldout,
                   int n, float scale) {
        e += n / 4;
        ca.s[idx] = {in, outp, cols / 4, ldout, e, scale};
    };
    seg(0, x,      xt,           Cc, Cc,   NROW * Cc, 1.f);
    seg(1, W_ckv,  wdown,        Ll, 512,  Cc * Ll,   1.f);
    seg(2, W_cq,   wdown + 256,  Ll, 512,  Cc * Ll,   1.f);
    seg(3, W_kc,   wkvup,        Cc, 2048, Ll * Cc,   1.f);
    seg(4, W_vc,   wkvup + 1024, Cc, 2048, Ll * Cc,   1.f);
    seg(5, W_qc,   wqc,          Cc, Cc,   Ll * Cc,   0.125f);
    seg(6, W_proj, wproj,        Cc, Cc,   Cc * Cc,   1.f);
    cvt_batched<<<(e + 255) / 256, 256>>>(ca);                        // launch 0

    // transpose interaction matrix (causal tiles only)
    dim3 gT(Tt / 32, Tt / 8, Bb);
    transpose_bias<<<gT, 256>>>(inter, biasT);                        // launch 1

    // merged down-projection: [4096,1024] @ [1024,512] -> kv_down|q_down
    dim3 gDown(512 / 128, NROW / 128);
    gemm_tc<<<gDown, 256, GEMM_SMEM>>>(xt, wdown, down, 512, Cc, Cc, 512, 512,
                                       nullptr, 1, nullptr);          // launch 2

    // merged kv up-projection: [4096,256] @ [256,2048] -> k|v
    dim3 gKV(2048 / 128, NROW / 128);
    gemm_tc<<<gKV, 256, GEMM_SMEM>>>(down, wkvup, kv, 2048, Ll, 512, 2048, 2048,
                                     nullptr, 1, nullptr);            // launch 3

    // q up-projection with pad-row zeroing (weights pre-scaled by D^-0.5)
    dim3 gQ(Cc / 128, NROW / 128);
    gemm_tc<<<gQ, 256, GEMM_SMEM>>>(down + 256, wqc, q, Cc, Ll, 512, Cc, Cc,
                                    nullptr, 1, pmask);               // launch 4

    // tensor-core flash attention: 128q x 64k tiles
    dim3 gAttn(Tt / BQ, Hh, Bb);
    attn_tc<<<gAttn, 256, ATTN_SMEM>>>(q, Cc, kv, kv + 1024, 2048, biasT,
                                       pmask, ctx);                   // launch 5

    // output projection with bias (final: full fp32)
    dim3 gProj(Cc / 128, NROW / 128);
    gemm_tc<<<gProj, 256, GEMM_SMEM>>>(ctx, wproj, out, Cc, Cc, Cc, Cc, Cc,
                                       b_proj, 0, nullptr);           // launch 6
}